// round 4
// baseline (speedup 1.0000x reference)
#include <cuda_runtime.h>
#include <math.h>

// ---------------------------------------------------------------------------
// Problem constants (fixed by the reference)
// ---------------------------------------------------------------------------
#define B_      2
#define T_      2048
#define D_      2048
#define NH      16
#define NKV     4
#define HD      128
#define M_TOK   (B_ * T_)          // 4096 tokens
#define QCOLS   (NH * HD)          // 2048
#define KVCOLS  (NKV * HD)         // 512

// ---------------------------------------------------------------------------
// Scratch (static __device__ — allocation-guard safe)
// ---------------------------------------------------------------------------
__device__ float g_q  [M_TOK * QCOLS];    // q projection, token-major [m][h*128+d]
__device__ float g_k  [M_TOK * KVCOLS];   // k projection, token-major
__device__ float g_v  [M_TOK * KVCOLS];   // v projection, token-major
__device__ float g_att[M_TOK * QCOLS];    // attention output, token-major

// ---------------------------------------------------------------------------
// SGEMM: C[M,N] = A[M,K] @ B[K,N], fp32, all dims multiples of tile sizes.
// 128x128 block tile, BK=8, 256 threads, 8x8 per-thread micro-tile.
// A tile stored transposed in smem for conflict-free float4 reads.
// ---------------------------------------------------------------------------
__global__ __launch_bounds__(256) void sgemm128(
    const float* __restrict__ A, const float* __restrict__ B,
    float* __restrict__ C, int K, int N)
{
    __shared__ float As[8][128];
    __shared__ float Bs[8][128];

    const int tid = threadIdx.x;
    const int tx  = tid & 15;
    const int ty  = tid >> 4;
    const int row0 = blockIdx.y * 128;
    const int col0 = blockIdx.x * 128;

    float acc[8][8];
#pragma unroll
    for (int i = 0; i < 8; i++)
#pragma unroll
        for (int j = 0; j < 8; j++) acc[i][j] = 0.0f;

    const int ar = tid >> 1;            // 0..127
    const int ac = (tid & 1) << 2;      // 0 or 4
    const int br = tid >> 5;            // 0..7
    const int bc = (tid & 31) << 2;     // 0..124

    const float* Ap = A + (size_t)(row0 + ar) * K + ac;
    const float* Bp = B + (size_t)br * N + col0 + bc;

    for (int k0 = 0; k0 < K; k0 += 8) {
        float4 av = *(const float4*)(Ap + k0);
        float4 bv = *(const float4*)(Bp + (size_t)k0 * N);
        As[ac + 0][ar] = av.x;
        As[ac + 1][ar] = av.y;
        As[ac + 2][ar] = av.z;
        As[ac + 3][ar] = av.w;
        *(float4*)&Bs[br][bc] = bv;
        __syncthreads();

#pragma unroll
        for (int kk = 0; kk < 8; kk++) {
            float a[8], b[8];
            float4 t;
            t = *(const float4*)&As[kk][ty * 8];     a[0]=t.x; a[1]=t.y; a[2]=t.z; a[3]=t.w;
            t = *(const float4*)&As[kk][ty * 8 + 4]; a[4]=t.x; a[5]=t.y; a[6]=t.z; a[7]=t.w;
            t = *(const float4*)&Bs[kk][tx * 8];     b[0]=t.x; b[1]=t.y; b[2]=t.z; b[3]=t.w;
            t = *(const float4*)&Bs[kk][tx * 8 + 4]; b[4]=t.x; b[5]=t.y; b[6]=t.z; b[7]=t.w;
#pragma unroll
            for (int i = 0; i < 8; i++)
#pragma unroll
                for (int j = 0; j < 8; j++)
                    acc[i][j] = fmaf(a[i], b[j], acc[i][j]);
        }
        __syncthreads();
    }

#pragma unroll
    for (int i = 0; i < 8; i++) {
        float* Cp = C + (size_t)(row0 + ty * 8 + i) * N + col0 + tx * 8;
        *(float4*)(Cp)     = make_float4(acc[i][0], acc[i][1], acc[i][2], acc[i][3]);
        *(float4*)(Cp + 4) = make_float4(acc[i][4], acc[i][5], acc[i][6], acc[i][7]);
    }
}

// ---------------------------------------------------------------------------
// RoPE: in-place rotary on q (16 heads) and k (4 heads), token-major layout.
// One thread per (token, head, pair): out[i]    = u1*cos - u2*sin
//                                     out[i+64] = u2*cos + u1*sin
// ang = t * theta^(-i/64), matching the reference's concat([ang, ang]).
// ---------------------------------------------------------------------------
__global__ void rope_kernel(float* __restrict__ q, float* __restrict__ k)
{
    const int PPT = (NH + NKV) * (HD / 2);   // 1280 pairs per token
    int idx = blockIdx.x * blockDim.x + threadIdx.x;
    if (idx >= M_TOK * PPT) return;

    int m    = idx / PPT;
    int r    = idx - m * PPT;
    int head = r >> 6;       // 0..19 (0..15 = q heads, 16..19 = k heads)
    int i    = r & 63;
    int t    = m & (T_ - 1); // position within sequence (T_ power of 2)

    float invf = (float)(1.0 / pow(1.0e6, (double)i / 64.0));
    float ang  = (float)t * invf;
    float s, c;
    sincosf(ang, &s, &c);

    float* base = (head < NH)
        ? (q + (size_t)m * QCOLS + head * HD)
        : (k + (size_t)m * KVCOLS + (head - NH) * HD);

    float u1 = base[i];
    float u2 = base[i + 64];
    base[i]      = u1 * c - u2 * s;
    base[i + 64] = u2 * c + u1 * s;
}

// ---------------------------------------------------------------------------
// Flash attention, fp32, causal, GQA (kv head = h/4).
// Grid: (T/64, NH, B). Block: 256 threads = 16x16.
// Per thread: S micro-tile 4 rows x 4 cols; O micro-tile 4 rows x 8 cols.
// smem: Qs[64][132], KsT[128][64] (K transposed), Vs[64][132], Ps[64][68].
// ---------------------------------------------------------------------------
#define FBM 64
#define FBN 64
#define QSS 132
#define VSS 132
#define PSS 68
#define SMEM_FLASH ((FBM*QSS + HD*FBN + FBM*VSS + FBM*PSS) * (int)sizeof(float)) // 117760 B

__global__ __launch_bounds__(256, 1) void flash_kernel(
    const float* __restrict__ Qg, const float* __restrict__ Kg,
    const float* __restrict__ Vg, float* __restrict__ Og)
{
    extern __shared__ float sm[];
    float* Qs  = sm;                    // [FBM][QSS]
    float* KsT = Qs  + FBM * QSS;       // [HD][FBN]
    float* Vs  = KsT + HD * FBN;        // [FBN][VSS]
    float* Ps  = Vs  + FBM * VSS;       // [FBM][PSS]

    const int qb  = blockIdx.x;
    const int h   = blockIdx.y;
    const int b   = blockIdx.z;
    const int kvh = h >> 2;
    const int tid = threadIdx.x;
    const int tx  = tid & 15;
    const int ty  = tid >> 4;
    const int q0  = qb * FBM;
    const float scale = 0.08838834764831845f;   // 1/sqrt(128)

    const float* Qbase = Qg + (size_t)b * T_ * QCOLS  + h   * HD;
    const float* Kbase = Kg + (size_t)b * T_ * KVCOLS + kvh * HD;
    const float* Vbase = Vg + (size_t)b * T_ * KVCOLS + kvh * HD;

    // Load Q tile [64][128]
    for (int l = tid; l < FBM * (HD / 4); l += 256) {
        int r  = l >> 5;
        int c4 = (l & 31) << 2;
        float4 v = *(const float4*)(Qbase + (size_t)(q0 + r) * QCOLS + c4);
        *(float4*)&Qs[r * QSS + c4] = v;
    }

    float m_i[4], l_i[4], acc[4][8];
#pragma unroll
    for (int i = 0; i < 4; i++) {
        m_i[i] = -1e30f;
        l_i[i] = 0.0f;
#pragma unroll
        for (int c = 0; c < 8; c++) acc[i][c] = 0.0f;
    }

    for (int kt = 0; kt <= qb; kt++) {
        __syncthreads();   // prior O-phase done with Ps/Vs/KsT (and Qs ready, 1st iter)
        const int s0 = kt * FBN;

        // Load K tile transposed: KsT[d][s]. s-contiguous lanes -> conflict-free STS.
        for (int l = tid; l < FBN * (HD / 4); l += 256) {
            int s  = l & 63;
            int d4 = (l >> 6) << 2;
            float4 v = *(const float4*)(Kbase + (size_t)(s0 + s) * KVCOLS + d4);
            KsT[(d4 + 0) * FBN + s] = v.x;
            KsT[(d4 + 1) * FBN + s] = v.y;
            KsT[(d4 + 2) * FBN + s] = v.z;
            KsT[(d4 + 3) * FBN + s] = v.w;
        }
        // Load V tile [64][128] row-major
        for (int l = tid; l < FBN * (HD / 4); l += 256) {
            int s  = l >> 5;
            int c4 = (l & 31) << 2;
            float4 v = *(const float4*)(Vbase + (size_t)(s0 + s) * KVCOLS + c4);
            *(float4*)&Vs[s * VSS + c4] = v;
        }
        __syncthreads();

        // ---- S = Q @ K^T : 4x4 per thread over k=0..127 (unrolled by 4) ----
        float sv[4][4];
#pragma unroll
        for (int i = 0; i < 4; i++)
#pragma unroll
            for (int j = 0; j < 4; j++) sv[i][j] = 0.0f;

        for (int k = 0; k < HD; k += 4) {
            float a[4][4], bb[4][4];
            float4 t;
#pragma unroll
            for (int i = 0; i < 4; i++) {
                t = *(const float4*)&Qs[(ty * 4 + i) * QSS + k];
                a[i][0] = t.x; a[i][1] = t.y; a[i][2] = t.z; a[i][3] = t.w;
            }
#pragma unroll
            for (int u = 0; u < 4; u++) {
                t = *(const float4*)&KsT[(k + u) * FBN + tx * 4];
                bb[u][0] = t.x; bb[u][1] = t.y; bb[u][2] = t.z; bb[u][3] = t.w;
            }
#pragma unroll
            for (int u = 0; u < 4; u++)
#pragma unroll
                for (int i = 0; i < 4; i++)
#pragma unroll
                    for (int j = 0; j < 4; j++)
                        sv[i][j] = fmaf(a[i][u], bb[u][j], sv[i][j]);
        }

#pragma unroll
        for (int i = 0; i < 4; i++)
#pragma unroll
            for (int j = 0; j < 4; j++) sv[i][j] *= scale;

        if (kt == qb) {   // diagonal tile: mask s > t  <=>  col > row
#pragma unroll
            for (int i = 0; i < 4; i++)
#pragma unroll
                for (int j = 0; j < 4; j++)
                    if (tx * 4 + j > ty * 4 + i) sv[i][j] = -3.0e38f;
        }

        // ---- Online softmax; row reductions across the 16 tx lanes ----
#pragma unroll
        for (int i = 0; i < 4; i++) {
            float mt = fmaxf(fmaxf(sv[i][0], sv[i][1]), fmaxf(sv[i][2], sv[i][3]));
#pragma unroll
            for (int off = 8; off >= 1; off >>= 1)
                mt = fmaxf(mt, __shfl_xor_sync(0xffffffffu, mt, off));
            float mnew = fmaxf(m_i[i], mt);
            float corr = expf(m_i[i] - mnew);
            float p0 = expf(sv[i][0] - mnew);
            float p1 = expf(sv[i][1] - mnew);
            float p2 = expf(sv[i][2] - mnew);
            float p3 = expf(sv[i][3] - mnew);
            float rs = (p0 + p1) + (p2 + p3);
#pragma unroll
            for (int off = 8; off >= 1; off >>= 1)
                rs += __shfl_xor_sync(0xffffffffu, rs, off);
            l_i[i] = l_i[i] * corr + rs;
            m_i[i] = mnew;
#pragma unroll
            for (int c = 0; c < 8; c++) acc[i][c] *= corr;
            *(float4*)&Ps[(ty * 4 + i) * PSS + tx * 4] = make_float4(p0, p1, p2, p3);
        }
        __syncthreads();

        // ---- O += P @ V : 4 rows x 8 cols per thread over s=0..63 ----
        for (int kk = 0; kk < FBN; kk += 4) {
            float p[4][4];
            float4 t;
#pragma unroll
            for (int i = 0; i < 4; i++) {
                t = *(const float4*)&Ps[(ty * 4 + i) * PSS + kk];
                p[i][0] = t.x; p[i][1] = t.y; p[i][2] = t.z; p[i][3] = t.w;
            }
#pragma unroll
            for (int u = 0; u < 4; u++) {
                float v0[4], v1[4];
                t = *(const float4*)&Vs[(kk + u) * VSS + tx * 8];
                v0[0] = t.x; v0[1] = t.y; v0[2] = t.z; v0[3] = t.w;
                t = *(const float4*)&Vs[(kk + u) * VSS + tx * 8 + 4];
                v1[0] = t.x; v1[1] = t.y; v1[2] = t.z; v1[3] = t.w;
#pragma unroll
                for (int i = 0; i < 4; i++) {
#pragma unroll
                    for (int c = 0; c < 4; c++)
                        acc[i][c] = fmaf(p[i][u], v0[c], acc[i][c]);
#pragma unroll
                    for (int c = 0; c < 4; c++)
                        acc[i][4 + c] = fmaf(p[i][u], v1[c], acc[i][4 + c]);
                }
            }
        }
    }

    // ---- Epilogue: O /= l, write token-major to g_att ----
    float* Obase = Og + (size_t)b * T_ * QCOLS + h * HD;
#pragma unroll
    for (int i = 0; i < 4; i++) {
        float inv = 1.0f / l_i[i];
        float* op = Obase + (size_t)(q0 + ty * 4 + i) * QCOLS + tx * 8;
        *(float4*)(op)     = make_float4(acc[i][0]*inv, acc[i][1]*inv, acc[i][2]*inv, acc[i][3]*inv);
        *(float4*)(op + 4) = make_float4(acc[i][4]*inv, acc[i][5]*inv, acc[i][6]*inv, acc[i][7]*inv);
    }
}

// ---------------------------------------------------------------------------
// Launch
// ---------------------------------------------------------------------------
extern "C" void kernel_launch(void* const* d_in, const int* in_sizes, int n_in,
                              void* d_out, int out_size)
{
    const float* x  = (const float*)d_in[0];
    const float* wq = (const float*)d_in[1];
    const float* wk = (const float*)d_in[2];
    const float* wv = (const float*)d_in[3];
    const float* wo = (const float*)d_in[4];
    float* out = (float*)d_out;

    float *q, *k, *v, *att;
    cudaGetSymbolAddress((void**)&q,   g_q);
    cudaGetSymbolAddress((void**)&k,   g_k);
    cudaGetSymbolAddress((void**)&v,   g_v);
    cudaGetSymbolAddress((void**)&att, g_att);

    cudaFuncSetAttribute(flash_kernel,
                         cudaFuncAttributeMaxDynamicSharedMemorySize, SMEM_FLASH);

    dim3 blk(256);

    // QKV projections (token-major outputs)
    sgemm128<<<dim3(QCOLS  / 128, M_TOK / 128), blk>>>(x, wq, q, D_, QCOLS);
    sgemm128<<<dim3(KVCOLS / 128, M_TOK / 128), blk>>>(x, wk, k, D_, KVCOLS);
    sgemm128<<<dim3(KVCOLS / 128, M_TOK / 128), blk>>>(x, wv, v, D_, KVCOLS);

    // RoPE on q and k (in-place)
    int total_pairs = M_TOK * (NH + NKV) * (HD / 2);
    rope_kernel<<<(total_pairs + 255) / 256, 256>>>(q, k);

    // Causal GQA flash attention
    flash_kernel<<<dim3(T_ / FBM, NH, B_), blk, SMEM_FLASH>>>(q, k, v, att);

    // Output projection
    sgemm128<<<dim3(D_ / 128, M_TOK / 128), blk>>>(att, wo, out, QCOLS, D_);
}

// round 5
// speedup vs baseline: 1.7034x; 1.7034x over previous
#include <cuda_runtime.h>
#include <math.h>
#include <stdint.h>

// ---------------------------------------------------------------------------
// Problem constants (fixed by the reference)
// ---------------------------------------------------------------------------
#define B_      2
#define T_      2048
#define D_      2048
#define NH      16
#define NKV     4
#define HD      128
#define M_TOK   (B_ * T_)          // 4096 tokens
#define QCOLS   (NH * HD)          // 2048
#define KVCOLS  (NKV * HD)         // 512

// ---------------------------------------------------------------------------
// Scratch (static __device__ — allocation-guard safe)
// ---------------------------------------------------------------------------
__device__ float g_q  [M_TOK * QCOLS];    // q projection, token-major [m][h*128+d]
__device__ float g_k  [M_TOK * KVCOLS];   // k projection, token-major
__device__ float g_v  [M_TOK * KVCOLS];   // v projection, token-major
__device__ float g_att[M_TOK * QCOLS];    // attention output, token-major

// ===========================================================================
// TF32 tensor-core GEMM:  C[M,N] = A[M,K] @ B[K,N], row-major, fp32 in/out.
// Block tile 128x128, BK=16, 256 threads (8 warps as 4x2), warp tile 32x64.
// mma.sync.aligned.m16n8k8.tf32 (legacy HMMA path on sm_103a).
// smem layout: fragment-permuted (4x4 col transpose within BK) + XOR swizzle
// so every fragment fetch is a conflict-free LDS.128. Inputs RNA-rounded to
// tf32 once, at smem-store time.
// ===========================================================================
#define BM  128
#define BN  128
#define BKG 16

__device__ __forceinline__ float to_tf32(float x) {
    uint32_t u;
    asm("cvt.rna.tf32.f32 %0, %1;" : "=r"(u) : "f"(x));
    return __uint_as_float(u);
}

__device__ __forceinline__ void mma_tf32(float4& d,
    uint32_t a0, uint32_t a1, uint32_t a2, uint32_t a3,
    uint32_t b0, uint32_t b1)
{
    asm volatile(
        "mma.sync.aligned.m16n8k8.row.col.f32.tf32.tf32.f32 "
        "{%0,%1,%2,%3}, {%4,%5,%6,%7}, {%8,%9}, {%0,%1,%2,%3};"
        : "+f"(d.x), "+f"(d.y), "+f"(d.z), "+f"(d.w)
        : "r"(a0), "r"(a1), "r"(a2), "r"(a3), "r"(b0), "r"(b1));
}

__global__ __launch_bounds__(256, 1) void gemm_tf32(
    const float* __restrict__ A, const float* __restrict__ Bm,
    float* __restrict__ C, int K, int N)
{
    __shared__ float As[2][BM * BKG];   // 16 KB x2
    __shared__ float Bs[2][BN * BKG];

    const int tid  = threadIdx.x;
    const int lane = tid & 31;
    const int wid  = tid >> 5;
    const int g    = lane >> 2;        // 0..7
    const int t    = lane & 3;         // 0..3
    const int wrow = wid & 3;          // 4 warp rows (M)
    const int wcol = wid >> 2;         // 2 warp cols (N)
    const int row0 = blockIdx.y * BM;
    const int col0 = blockIdx.x * BN;

    float4 c[2][8];
#pragma unroll
    for (int i = 0; i < 2; i++)
#pragma unroll
        for (int j = 0; j < 8; j++) c[i][j] = make_float4(0.f, 0.f, 0.f, 0.f);

    // Global-load assignment:
    //   A tile 128x16 = 512 float4: idx in {tid, tid+256}: r=idx>>2, quad=idx&3
    //   B tile 16x128 = 512 float4: idx in {tid, tid+256}: rr=idx>>5, cq=idx&31
    const int ar0 = tid >> 2;                 // 0..63  (second: +64)
    const int aq4 = (tid & 3) << 2;           // col offset 0,4,8,12
    const int aqi = tid & 3;                  // inner quad index
    const int br0 = tid >> 5;                 // 0..7   (second: +8)
    const int bc4 = (tid & 31) << 2;          // col offset 0..124

    float4 ra[2], rb[2];
    const int nk = K / BKG;

    // ---- prologue: load + store tile 0 ----
    {
        ra[0] = *(const float4*)(A + (size_t)(row0 + ar0)      * K + aq4);
        ra[1] = *(const float4*)(A + (size_t)(row0 + ar0 + 64) * K + aq4);
        rb[0] = *(const float4*)(Bm + (size_t)(br0)     * N + col0 + bc4);
        rb[1] = *(const float4*)(Bm + (size_t)(br0 + 8) * N + col0 + bc4);
    }
#pragma unroll
    for (int u = 0; u < 2; u++) {
        int r = ar0 + u * 64;
        float va[4] = { ra[u].x, ra[u].y, ra[u].z, ra[u].w };
#pragma unroll
        for (int e = 0; e < 4; e++)
            As[0][r * BKG + ((e ^ (r & 3)) << 2) + aqi] = to_tf32(va[e]);
        int rr = br0 + u * 8;
        float vb[4] = { rb[u].x, rb[u].y, rb[u].z, rb[u].w };
#pragma unroll
        for (int e = 0; e < 4; e++) {
            int cN = bc4 + e;
            Bs[0][cN * BKG + (((rr & 3) ^ (cN & 3)) << 2) + (rr >> 2)] = to_tf32(vb[e]);
        }
    }

    const int aswz = (t ^ (g & 3)) << 2;   // fragment-read swizzle offset

    for (int kb = 0; kb < nk; kb++) {
        __syncthreads();
        const int buf  = kb & 1;
        const bool more = (kb + 1 < nk);

        // issue next tile's global loads (latency hidden by compute)
        if (more) {
            const float* Ap = A + (size_t)kb * BKG + BKG;
            ra[0] = *(const float4*)(Ap + (size_t)(row0 + ar0)      * K + aq4);
            ra[1] = *(const float4*)(Ap + (size_t)(row0 + ar0 + 64) * K + aq4);
            const float* Bp = Bm + (size_t)(kb + 1) * BKG * N;
            rb[0] = *(const float4*)(Bp + (size_t)(br0)     * N + col0 + bc4);
            rb[1] = *(const float4*)(Bp + (size_t)(br0 + 8) * N + col0 + bc4);
        }

        // ---- fragment loads (all conflict-free LDS.128) ----
        float4 afl[2], afh[2], bf[8];
#pragma unroll
        for (int i = 0; i < 2; i++) {
            int rl = wrow * 32 + i * 16 + g;
            afl[i] = *(const float4*)&As[buf][rl * BKG + aswz];
            afh[i] = *(const float4*)&As[buf][(rl + 8) * BKG + aswz];
        }
#pragma unroll
        for (int j = 0; j < 8; j++) {
            int cN = wcol * 64 + j * 8 + g;
            bf[j] = *(const float4*)&Bs[buf][cN * BKG + aswz];
        }

        // ---- 2 k-steps x 2 m-tiles x 8 n-tiles of m16n8k8 ----
#pragma unroll
        for (int i = 0; i < 2; i++) {
            uint32_t a0 = __float_as_uint(afl[i].x), a1 = __float_as_uint(afh[i].x);
            uint32_t a2 = __float_as_uint(afl[i].y), a3 = __float_as_uint(afh[i].y);
#pragma unroll
            for (int j = 0; j < 8; j++)
                mma_tf32(c[i][j], a0, a1, a2, a3,
                         __float_as_uint(bf[j].x), __float_as_uint(bf[j].y));
        }
#pragma unroll
        for (int i = 0; i < 2; i++) {
            uint32_t a0 = __float_as_uint(afl[i].z), a1 = __float_as_uint(afh[i].z);
            uint32_t a2 = __float_as_uint(afl[i].w), a3 = __float_as_uint(afh[i].w);
#pragma unroll
            for (int j = 0; j < 8; j++)
                mma_tf32(c[i][j], a0, a1, a2, a3,
                         __float_as_uint(bf[j].z), __float_as_uint(bf[j].w));
        }

        // ---- scatter next tile into the other buffer ----
        if (more) {
            const int nbuf = buf ^ 1;
#pragma unroll
            for (int u = 0; u < 2; u++) {
                int r = ar0 + u * 64;
                float va[4] = { ra[u].x, ra[u].y, ra[u].z, ra[u].w };
#pragma unroll
                for (int e = 0; e < 4; e++)
                    As[nbuf][r * BKG + ((e ^ (r & 3)) << 2) + aqi] = to_tf32(va[e]);
                int rr = br0 + u * 8;
                float vb[4] = { rb[u].x, rb[u].y, rb[u].z, rb[u].w };
#pragma unroll
                for (int e = 0; e < 4; e++) {
                    int cN = bc4 + e;
                    Bs[nbuf][cN * BKG + (((rr & 3) ^ (cN & 3)) << 2) + (rr >> 2)] = to_tf32(vb[e]);
                }
            }
        }
    }

    // ---- epilogue ----
#pragma unroll
    for (int i = 0; i < 2; i++) {
        int r = row0 + wrow * 32 + i * 16 + g;
#pragma unroll
        for (int j = 0; j < 8; j++) {
            int cc = col0 + wcol * 64 + j * 8 + 2 * t;
            *(float2*)(C + (size_t)r * N + cc)       = make_float2(c[i][j].x, c[i][j].y);
            *(float2*)(C + (size_t)(r + 8) * N + cc) = make_float2(c[i][j].z, c[i][j].w);
        }
    }
}

// ---------------------------------------------------------------------------
// RoPE: in-place rotary on q (16 heads) and k (4 heads), token-major layout.
// ---------------------------------------------------------------------------
__global__ void rope_kernel(float* __restrict__ q, float* __restrict__ k)
{
    const int PPT = (NH + NKV) * (HD / 2);   // 1280 pairs per token
    int idx = blockIdx.x * blockDim.x + threadIdx.x;
    if (idx >= M_TOK * PPT) return;

    int m    = idx / PPT;
    int r    = idx - m * PPT;
    int head = r >> 6;       // 0..19 (0..15 = q heads, 16..19 = k heads)
    int i    = r & 63;
    int t    = m & (T_ - 1); // position within sequence

    float invf = (float)(1.0 / pow(1.0e6, (double)i / 64.0));
    float ang  = (float)t * invf;
    float s, c;
    sincosf(ang, &s, &c);

    float* base = (head < NH)
        ? (q + (size_t)m * QCOLS + head * HD)
        : (k + (size_t)m * KVCOLS + (head - NH) * HD);

    float u1 = base[i];
    float u2 = base[i + 64];
    base[i]      = u1 * c - u2 * s;
    base[i + 64] = u2 * c + u1 * s;
}

// ---------------------------------------------------------------------------
// Flash attention, fp32, causal, GQA (kv head = h/4).  (unchanged from R3)
// ---------------------------------------------------------------------------
#define FBM 64
#define FBN 64
#define QSS 132
#define VSS 132
#define PSS 68
#define SMEM_FLASH ((FBM*QSS + HD*FBN + FBM*VSS + FBM*PSS) * (int)sizeof(float)) // 117760 B

__global__ __launch_bounds__(256, 1) void flash_kernel(
    const float* __restrict__ Qg, const float* __restrict__ Kg,
    const float* __restrict__ Vg, float* __restrict__ Og)
{
    extern __shared__ float sm[];
    float* Qs  = sm;                    // [FBM][QSS]
    float* KsT = Qs  + FBM * QSS;       // [HD][FBN]
    float* Vs  = KsT + HD * FBN;        // [FBN][VSS]
    float* Ps  = Vs  + FBM * VSS;       // [FBM][PSS]

    const int qb  = blockIdx.x;
    const int h   = blockIdx.y;
    const int b   = blockIdx.z;
    const int kvh = h >> 2;
    const int tid = threadIdx.x;
    const int tx  = tid & 15;
    const int ty  = tid >> 4;
    const int q0  = qb * FBM;
    const float scale = 0.08838834764831845f;   // 1/sqrt(128)

    const float* Qbase = Qg + (size_t)b * T_ * QCOLS  + h   * HD;
    const float* Kbase = Kg + (size_t)b * T_ * KVCOLS + kvh * HD;
    const float* Vbase = Vg + (size_t)b * T_ * KVCOLS + kvh * HD;

    for (int l = tid; l < FBM * (HD / 4); l += 256) {
        int r  = l >> 5;
        int c4 = (l & 31) << 2;
        float4 v = *(const float4*)(Qbase + (size_t)(q0 + r) * QCOLS + c4);
        *(float4*)&Qs[r * QSS + c4] = v;
    }

    float m_i[4], l_i[4], acc[4][8];
#pragma unroll
    for (int i = 0; i < 4; i++) {
        m_i[i] = -1e30f;
        l_i[i] = 0.0f;
#pragma unroll
        for (int c = 0; c < 8; c++) acc[i][c] = 0.0f;
    }

    for (int kt = 0; kt <= qb; kt++) {
        __syncthreads();
        const int s0 = kt * FBN;

        for (int l = tid; l < FBN * (HD / 4); l += 256) {
            int s  = l & 63;
            int d4 = (l >> 6) << 2;
            float4 v = *(const float4*)(Kbase + (size_t)(s0 + s) * KVCOLS + d4);
            KsT[(d4 + 0) * FBN + s] = v.x;
            KsT[(d4 + 1) * FBN + s] = v.y;
            KsT[(d4 + 2) * FBN + s] = v.z;
            KsT[(d4 + 3) * FBN + s] = v.w;
        }
        for (int l = tid; l < FBN * (HD / 4); l += 256) {
            int s  = l >> 5;
            int c4 = (l & 31) << 2;
            float4 v = *(const float4*)(Vbase + (size_t)(s0 + s) * KVCOLS + c4);
            *(float4*)&Vs[s * VSS + c4] = v;
        }
        __syncthreads();

        float sv[4][4];
#pragma unroll
        for (int i = 0; i < 4; i++)
#pragma unroll
            for (int j = 0; j < 4; j++) sv[i][j] = 0.0f;

        for (int k = 0; k < HD; k += 4) {
            float a[4][4], bb[4][4];
            float4 t;
#pragma unroll
            for (int i = 0; i < 4; i++) {
                t = *(const float4*)&Qs[(ty * 4 + i) * QSS + k];
                a[i][0] = t.x; a[i][1] = t.y; a[i][2] = t.z; a[i][3] = t.w;
            }
#pragma unroll
            for (int u = 0; u < 4; u++) {
                t = *(const float4*)&KsT[(k + u) * FBN + tx * 4];
                bb[u][0] = t.x; bb[u][1] = t.y; bb[u][2] = t.z; bb[u][3] = t.w;
            }
#pragma unroll
            for (int u = 0; u < 4; u++)
#pragma unroll
                for (int i = 0; i < 4; i++)
#pragma unroll
                    for (int j = 0; j < 4; j++)
                        sv[i][j] = fmaf(a[i][u], bb[u][j], sv[i][j]);
        }

#pragma unroll
        for (int i = 0; i < 4; i++)
#pragma unroll
            for (int j = 0; j < 4; j++) sv[i][j] *= scale;

        if (kt == qb) {
#pragma unroll
            for (int i = 0; i < 4; i++)
#pragma unroll
                for (int j = 0; j < 4; j++)
                    if (tx * 4 + j > ty * 4 + i) sv[i][j] = -3.0e38f;
        }

#pragma unroll
        for (int i = 0; i < 4; i++) {
            float mt = fmaxf(fmaxf(sv[i][0], sv[i][1]), fmaxf(sv[i][2], sv[i][3]));
#pragma unroll
            for (int off = 8; off >= 1; off >>= 1)
                mt = fmaxf(mt, __shfl_xor_sync(0xffffffffu, mt, off));
            float mnew = fmaxf(m_i[i], mt);
            float corr = expf(m_i[i] - mnew);
            float p0 = expf(sv[i][0] - mnew);
            float p1 = expf(sv[i][1] - mnew);
            float p2 = expf(sv[i][2] - mnew);
            float p3 = expf(sv[i][3] - mnew);
            float rs = (p0 + p1) + (p2 + p3);
#pragma unroll
            for (int off = 8; off >= 1; off >>= 1)
                rs += __shfl_xor_sync(0xffffffffu, rs, off);
            l_i[i] = l_i[i] * corr + rs;
            m_i[i] = mnew;
#pragma unroll
            for (int c = 0; c < 8; c++) acc[i][c] *= corr;
            *(float4*)&Ps[(ty * 4 + i) * PSS + tx * 4] = make_float4(p0, p1, p2, p3);
        }
        __syncthreads();

        for (int kk = 0; kk < FBN; kk += 4) {
            float p[4][4];
            float4 t;
#pragma unroll
            for (int i = 0; i < 4; i++) {
                t = *(const float4*)&Ps[(ty * 4 + i) * PSS + kk];
                p[i][0] = t.x; p[i][1] = t.y; p[i][2] = t.z; p[i][3] = t.w;
            }
#pragma unroll
            for (int u = 0; u < 4; u++) {
                float v0[4], v1[4];
                t = *(const float4*)&Vs[(kk + u) * VSS + tx * 8];
                v0[0] = t.x; v0[1] = t.y; v0[2] = t.z; v0[3] = t.w;
                t = *(const float4*)&Vs[(kk + u) * VSS + tx * 8 + 4];
                v1[0] = t.x; v1[1] = t.y; v1[2] = t.z; v1[3] = t.w;
#pragma unroll
                for (int i = 0; i < 4; i++) {
#pragma unroll
                    for (int c = 0; c < 4; c++)
                        acc[i][c] = fmaf(p[i][u], v0[c], acc[i][c]);
#pragma unroll
                    for (int c = 0; c < 4; c++)
                        acc[i][4 + c] = fmaf(p[i][u], v1[c], acc[i][4 + c]);
                }
            }
        }
    }

    float* Obase = Og + (size_t)b * T_ * QCOLS + h * HD;
#pragma unroll
    for (int i = 0; i < 4; i++) {
        float inv = 1.0f / l_i[i];
        float* op = Obase + (size_t)(q0 + ty * 4 + i) * QCOLS + tx * 8;
        *(float4*)(op)     = make_float4(acc[i][0]*inv, acc[i][1]*inv, acc[i][2]*inv, acc[i][3]*inv);
        *(float4*)(op + 4) = make_float4(acc[i][4]*inv, acc[i][5]*inv, acc[i][6]*inv, acc[i][7]*inv);
    }
}

// ---------------------------------------------------------------------------
// Launch
// ---------------------------------------------------------------------------
extern "C" void kernel_launch(void* const* d_in, const int* in_sizes, int n_in,
                              void* d_out, int out_size)
{
    const float* x  = (const float*)d_in[0];
    const float* wq = (const float*)d_in[1];
    const float* wk = (const float*)d_in[2];
    const float* wv = (const float*)d_in[3];
    const float* wo = (const float*)d_in[4];
    float* out = (float*)d_out;

    float *q, *k, *v, *att;
    cudaGetSymbolAddress((void**)&q,   g_q);
    cudaGetSymbolAddress((void**)&k,   g_k);
    cudaGetSymbolAddress((void**)&v,   g_v);
    cudaGetSymbolAddress((void**)&att, g_att);

    cudaFuncSetAttribute(flash_kernel,
                         cudaFuncAttributeMaxDynamicSharedMemorySize, SMEM_FLASH);

    dim3 blk(256);

    // QKV projections (tf32 tensor cores, token-major outputs)
    gemm_tf32<<<dim3(QCOLS  / BN, M_TOK / BM), blk>>>(x, wq, q, D_, QCOLS);
    gemm_tf32<<<dim3(KVCOLS / BN, M_TOK / BM), blk>>>(x, wk, k, D_, KVCOLS);
    gemm_tf32<<<dim3(KVCOLS / BN, M_TOK / BM), blk>>>(x, wv, v, D_, KVCOLS);

    // RoPE on q and k (in-place)
    int total_pairs = M_TOK * (NH + NKV) * (HD / 2);
    rope_kernel<<<(total_pairs + 255) / 256, 256>>>(q, k);

    // Causal GQA flash attention
    flash_kernel<<<dim3(T_ / FBM, NH, B_), blk, SMEM_FLASH>>>(q, k, v, att);

    // Output projection (tf32 tensor cores)
    gemm_tf32<<<dim3(D_ / BN, M_TOK / BM), blk>>>(att, wo, out, QCOLS, D_);
}

// round 6
// speedup vs baseline: 2.8205x; 1.6558x over previous
#include <cuda_runtime.h>
#include <math.h>
#include <stdint.h>

// ---------------------------------------------------------------------------
// Problem constants
// ---------------------------------------------------------------------------
#define B_      2
#define T_      2048
#define D_      2048
#define NH      16
#define NKV     4
#define HD      128
#define M_TOK   (B_ * T_)          // 4096
#define QCOLS   (NH * HD)          // 2048
#define KVCOLS  (NKV * HD)         // 512

// ---------------------------------------------------------------------------
// Scratch
// ---------------------------------------------------------------------------
__device__ float g_q  [M_TOK * QCOLS];
__device__ float g_k  [M_TOK * KVCOLS];
__device__ float g_v  [M_TOK * KVCOLS];
__device__ float g_att[M_TOK * QCOLS];
__device__ float g_invf[64];

// ---------------------------------------------------------------------------
// tf32 helpers
// ---------------------------------------------------------------------------
__device__ __forceinline__ float to_tf32(float x) {
    uint32_t u;
    asm("cvt.rna.tf32.f32 %0, %1;" : "=r"(u) : "f"(x));
    return __uint_as_float(u);
}
__device__ __forceinline__ uint32_t f2u(float x) { return __float_as_uint(x); }

__device__ __forceinline__ void mma_tf32(float4& d,
    uint32_t a0, uint32_t a1, uint32_t a2, uint32_t a3,
    uint32_t b0, uint32_t b1)
{
    asm volatile(
        "mma.sync.aligned.m16n8k8.row.col.f32.tf32.tf32.f32 "
        "{%0,%1,%2,%3}, {%4,%5,%6,%7}, {%8,%9}, {%0,%1,%2,%3};"
        : "+f"(d.x), "+f"(d.y), "+f"(d.z), "+f"(d.w)
        : "r"(a0), "r"(a1), "r"(a2), "r"(a3), "r"(b0), "r"(b1));
}

// ===========================================================================
// TF32 GEMM (unchanged from R4 — validated at 5.5e-4)
// ===========================================================================
#define BM  128
#define BN  128
#define BKG 16

__global__ __launch_bounds__(256, 1) void gemm_tf32(
    const float* __restrict__ A, const float* __restrict__ Bm,
    float* __restrict__ C, int K, int N)
{
    __shared__ float As[2][BM * BKG];
    __shared__ float Bs[2][BN * BKG];

    const int tid  = threadIdx.x;
    const int lane = tid & 31;
    const int wid  = tid >> 5;
    const int g    = lane >> 2;
    const int t    = lane & 3;
    const int wrow = wid & 3;
    const int wcol = wid >> 2;
    const int row0 = blockIdx.y * BM;
    const int col0 = blockIdx.x * BN;

    float4 c[2][8];
#pragma unroll
    for (int i = 0; i < 2; i++)
#pragma unroll
        for (int j = 0; j < 8; j++) c[i][j] = make_float4(0.f, 0.f, 0.f, 0.f);

    const int ar0 = tid >> 2;
    const int aq4 = (tid & 3) << 2;
    const int aqi = tid & 3;
    const int br0 = tid >> 5;
    const int bc4 = (tid & 31) << 2;

    float4 ra[2], rb[2];
    const int nk = K / BKG;

    {
        ra[0] = *(const float4*)(A + (size_t)(row0 + ar0)      * K + aq4);
        ra[1] = *(const float4*)(A + (size_t)(row0 + ar0 + 64) * K + aq4);
        rb[0] = *(const float4*)(Bm + (size_t)(br0)     * N + col0 + bc4);
        rb[1] = *(const float4*)(Bm + (size_t)(br0 + 8) * N + col0 + bc4);
    }
#pragma unroll
    for (int u = 0; u < 2; u++) {
        int r = ar0 + u * 64;
        float va[4] = { ra[u].x, ra[u].y, ra[u].z, ra[u].w };
#pragma unroll
        for (int e = 0; e < 4; e++)
            As[0][r * BKG + ((e ^ (r & 3)) << 2) + aqi] = to_tf32(va[e]);
        int rr = br0 + u * 8;
        float vb[4] = { rb[u].x, rb[u].y, rb[u].z, rb[u].w };
#pragma unroll
        for (int e = 0; e < 4; e++) {
            int cN = bc4 + e;
            Bs[0][cN * BKG + (((rr & 3) ^ (cN & 3)) << 2) + (rr >> 2)] = to_tf32(vb[e]);
        }
    }

    const int aswz = (t ^ (g & 3)) << 2;

    for (int kb = 0; kb < nk; kb++) {
        __syncthreads();
        const int buf  = kb & 1;
        const bool more = (kb + 1 < nk);

        if (more) {
            const float* Ap = A + (size_t)kb * BKG + BKG;
            ra[0] = *(const float4*)(Ap + (size_t)(row0 + ar0)      * K + aq4);
            ra[1] = *(const float4*)(Ap + (size_t)(row0 + ar0 + 64) * K + aq4);
            const float* Bp = Bm + (size_t)(kb + 1) * BKG * N;
            rb[0] = *(const float4*)(Bp + (size_t)(br0)     * N + col0 + bc4);
            rb[1] = *(const float4*)(Bp + (size_t)(br0 + 8) * N + col0 + bc4);
        }

        float4 afl[2], afh[2], bf[8];
#pragma unroll
        for (int i = 0; i < 2; i++) {
            int rl = wrow * 32 + i * 16 + g;
            afl[i] = *(const float4*)&As[buf][rl * BKG + aswz];
            afh[i] = *(const float4*)&As[buf][(rl + 8) * BKG + aswz];
        }
#pragma unroll
        for (int j = 0; j < 8; j++) {
            int cN = wcol * 64 + j * 8 + g;
            bf[j] = *(const float4*)&Bs[buf][cN * BKG + aswz];
        }

#pragma unroll
        for (int i = 0; i < 2; i++) {
            uint32_t a0 = f2u(afl[i].x), a1 = f2u(afh[i].x);
            uint32_t a2 = f2u(afl[i].y), a3 = f2u(afh[i].y);
#pragma unroll
            for (int j = 0; j < 8; j++)
                mma_tf32(c[i][j], a0, a1, a2, a3, f2u(bf[j].x), f2u(bf[j].y));
        }
#pragma unroll
        for (int i = 0; i < 2; i++) {
            uint32_t a0 = f2u(afl[i].z), a1 = f2u(afh[i].z);
            uint32_t a2 = f2u(afl[i].w), a3 = f2u(afh[i].w);
#pragma unroll
            for (int j = 0; j < 8; j++)
                mma_tf32(c[i][j], a0, a1, a2, a3, f2u(bf[j].z), f2u(bf[j].w));
        }

        if (more) {
            const int nbuf = buf ^ 1;
#pragma unroll
            for (int u = 0; u < 2; u++) {
                int r = ar0 + u * 64;
                float va[4] = { ra[u].x, ra[u].y, ra[u].z, ra[u].w };
#pragma unroll
                for (int e = 0; e < 4; e++)
                    As[nbuf][r * BKG + ((e ^ (r & 3)) << 2) + aqi] = to_tf32(va[e]);
                int rr = br0 + u * 8;
                float vb[4] = { rb[u].x, rb[u].y, rb[u].z, rb[u].w };
#pragma unroll
                for (int e = 0; e < 4; e++) {
                    int cN = bc4 + e;
                    Bs[nbuf][cN * BKG + (((rr & 3) ^ (cN & 3)) << 2) + (rr >> 2)] = to_tf32(vb[e]);
                }
            }
        }
    }

#pragma unroll
    for (int i = 0; i < 2; i++) {
        int r = row0 + wrow * 32 + i * 16 + g;
#pragma unroll
        for (int j = 0; j < 8; j++) {
            int cc = col0 + wcol * 64 + j * 8 + 2 * t;
            *(float2*)(C + (size_t)r * N + cc)       = make_float2(c[i][j].x, c[i][j].y);
            *(float2*)(C + (size_t)(r + 8) * N + cc) = make_float2(c[i][j].z, c[i][j].w);
        }
    }
}

// ---------------------------------------------------------------------------
// RoPE: invf table (FP64 pow computed ONCE by 64 threads, not 5.2M times)
// ---------------------------------------------------------------------------
__global__ void init_invf_kernel()
{
    int i = threadIdx.x;
    if (i < 64)
        g_invf[i] = (float)(1.0 / pow(1.0e6, (double)i / 64.0));
}

__global__ void rope_kernel(float* __restrict__ q, float* __restrict__ k)
{
    const int PPT = (NH + NKV) * (HD / 2);   // 1280
    int idx = blockIdx.x * blockDim.x + threadIdx.x;
    if (idx >= M_TOK * PPT) return;

    int m    = idx / PPT;
    int r    = idx - m * PPT;
    int head = r >> 6;
    int i    = r & 63;
    int t    = m & (T_ - 1);

    float ang = (float)t * g_invf[i];
    float s, c;
    sincosf(ang, &s, &c);

    float* base = (head < NH)
        ? (q + (size_t)m * QCOLS + head * HD)
        : (k + (size_t)m * KVCOLS + (head - NH) * HD);

    float u1 = base[i];
    float u2 = base[i + 64];
    base[i]      = u1 * c - u2 * s;
    base[i + 64] = u2 * c + u1 * s;
}

// ===========================================================================
// TF32 tensor-core flash attention. Causal, GQA.
// Grid (T/64, NH, B), 128 threads = 4 warps; warp owns 16 q rows.
// smem chunked layouts (16-wide k chunks, pad-swizzled for conflict-free LDS):
//   Qs/Ks: 8 chunks x (64 rows x 16) stride 1028
//   Vs   : 4 chunks x (128 dims x 16) stride 2064   (B operand of P@V)
//   Ps   : 4 chunks x (64 rows x 16) stride 1028    (A operand of P@V)
// ===========================================================================
#define QS_F   (8 * 1028)          // 8224 floats
#define KS_F   (8 * 1028)
#define VS_F   (4 * 2064)          // 8256
#define PS_F   (4 * 1028)          // 4112
#define FLASH_SMEM ((QS_F + KS_F + VS_F + PS_F) * (int)sizeof(float))  // 115264 B

__global__ __launch_bounds__(128, 1) void flash_tf32(
    const float* __restrict__ Qg, const float* __restrict__ Kg,
    const float* __restrict__ Vg, float* __restrict__ Og)
{
    extern __shared__ float sm[];
    float* Qs = sm;
    float* Ks = Qs + QS_F;
    float* Vs = Ks + KS_F;
    float* Ps = Vs + VS_F;
    const float4* Qs4 = (const float4*)Qs;
    const float4* Ks4 = (const float4*)Ks;
    const float4* Vs4 = (const float4*)Vs;
    const float4* Ps4 = (const float4*)Ps;

    const int tid  = threadIdx.x;
    const int lane = tid & 31;
    const int wid  = tid >> 5;
    const int g    = lane >> 2;
    const int t    = lane & 3;
    const int sw   = t ^ (g & 3);          // float4-unit swizzle offset
    const int qb   = blockIdx.x;
    const int h    = blockIdx.y;
    const int b    = blockIdx.z;
    const int kvh  = h >> 2;
    const int q0   = qb * 64;
    const int rl   = wid * 16 + g;         // warp-local q row (rl & 3 == g & 3)
    const float scale = 0.08838834764831845f;

    const float* Qbase = Qg + (size_t)b * T_ * QCOLS  + h   * HD;
    const float* Kbase = Kg + (size_t)b * T_ * KVCOLS + kvh * HD;
    const float* Vbase = Vg + (size_t)b * T_ * KVCOLS + kvh * HD;

    // ---- load Q tile [64 rows][128 dims] into chunked A-layout ----
    for (int l = tid; l < 2048; l += 128) {
        int r  = l >> 5;
        int d4 = (l & 31) << 2;
        float4 v = *(const float4*)(Qbase + (size_t)(q0 + r) * QCOLS + d4);
        int base = (d4 >> 4) * 1028 + r * 16 + ((d4 >> 2) & 3);
        int r3 = r & 3;
        Qs[base + ((0 ^ r3) << 2)] = to_tf32(v.x);
        Qs[base + ((1 ^ r3) << 2)] = to_tf32(v.y);
        Qs[base + ((2 ^ r3) << 2)] = to_tf32(v.z);
        Qs[base + ((3 ^ r3) << 2)] = to_tf32(v.w);
    }

    float4 o[16];
#pragma unroll
    for (int j = 0; j < 16; j++) o[j] = make_float4(0.f, 0.f, 0.f, 0.f);
    float m0 = -1e30f, m1 = -1e30f, l0 = 0.f, l1 = 0.f;

    for (int kt = 0; kt <= qb; kt++) {
        __syncthreads();
        const int s0 = kt * 64;

        // K tile -> B-layout [token n][k=dim], chunked (lanes span dims; STS conflict-free)
        for (int l = tid; l < 2048; l += 128) {
            int s  = l >> 5;
            int d4 = (l & 31) << 2;
            float4 v = *(const float4*)(Kbase + (size_t)(s0 + s) * KVCOLS + d4);
            int base = (d4 >> 4) * 1028 + s * 16 + ((d4 >> 2) & 3);
            int s3 = s & 3;
            Ks[base + ((0 ^ s3) << 2)] = to_tf32(v.x);
            Ks[base + ((1 ^ s3) << 2)] = to_tf32(v.y);
            Ks[base + ((2 ^ s3) << 2)] = to_tf32(v.z);
            Ks[base + ((3 ^ s3) << 2)] = to_tf32(v.w);
        }
        // V tile -> B-layout [dim n][k=token], chunked (lanes span tokens)
        for (int l = tid; l < 2048; l += 128) {
            int s  = l & 63;
            int d4 = (l >> 6) << 2;
            float4 v = *(const float4*)(Vbase + (size_t)(s0 + s) * KVCOLS + d4);
            int s3 = s & 3;
            int cb = (s >> 4) * 2064 + ((s >> 2) & 3);
            Vs[cb + (d4 + 0) * 16 + ((s3 ^ 0) << 2)] = to_tf32(v.x);
            Vs[cb + (d4 + 1) * 16 + ((s3 ^ 1) << 2)] = to_tf32(v.y);
            Vs[cb + (d4 + 2) * 16 + ((s3 ^ 2) << 2)] = to_tf32(v.z);
            Vs[cb + (d4 + 3) * 16 + ((s3 ^ 3) << 2)] = to_tf32(v.w);
        }
        __syncthreads();

        // ---- S = Q @ K^T  (warp: m16 x n64 x k128) ----
        float4 c[8];
#pragma unroll
        for (int j = 0; j < 8; j++) c[j] = make_float4(0.f, 0.f, 0.f, 0.f);

#pragma unroll
        for (int kc = 0; kc < 8; kc++) {
            float4 aL = Qs4[kc * 257 + rl * 4 + sw];
            float4 aH = Qs4[kc * 257 + (rl + 8) * 4 + sw];
            uint32_t x0 = f2u(aL.x), x1 = f2u(aH.x), x2 = f2u(aL.y), x3 = f2u(aH.y);
            uint32_t z0 = f2u(aL.z), z1 = f2u(aH.z), z2 = f2u(aL.w), z3 = f2u(aH.w);
#pragma unroll
            for (int j = 0; j < 8; j++) {
                float4 bv = Ks4[kc * 257 + (8 * j + g) * 4 + sw];
                mma_tf32(c[j], x0, x1, x2, x3, f2u(bv.x), f2u(bv.y));
                mma_tf32(c[j], z0, z1, z2, z3, f2u(bv.z), f2u(bv.w));
            }
        }

#pragma unroll
        for (int j = 0; j < 8; j++) {
            c[j].x *= scale; c[j].y *= scale; c[j].z *= scale; c[j].w *= scale;
        }

        if (kt == qb) {   // diagonal tile: mask kv col > q row
            const int row_lo = q0 + rl, row_hi = row_lo + 8;
#pragma unroll
            for (int j = 0; j < 8; j++) {
                int col = s0 + 8 * j + 2 * t;
                if (col     > row_lo) c[j].x = -1e30f;
                if (col + 1 > row_lo) c[j].y = -1e30f;
                if (col     > row_hi) c[j].z = -1e30f;
                if (col + 1 > row_hi) c[j].w = -1e30f;
            }
        }

        // ---- online softmax (rows rl via x/y, rl+8 via z/w) ----
        float mt0 = -1e30f, mt1 = -1e30f;
#pragma unroll
        for (int j = 0; j < 8; j++) {
            mt0 = fmaxf(mt0, fmaxf(c[j].x, c[j].y));
            mt1 = fmaxf(mt1, fmaxf(c[j].z, c[j].w));
        }
#pragma unroll
        for (int off = 1; off <= 2; off <<= 1) {
            mt0 = fmaxf(mt0, __shfl_xor_sync(0xffffffffu, mt0, off));
            mt1 = fmaxf(mt1, __shfl_xor_sync(0xffffffffu, mt1, off));
        }
        float m0n = fmaxf(m0, mt0), m1n = fmaxf(m1, mt1);
        float corr0 = __expf(m0 - m0n), corr1 = __expf(m1 - m1n);

        float rs0 = 0.f, rs1 = 0.f;
#pragma unroll
        for (int j = 0; j < 8; j++) {
            c[j].x = __expf(c[j].x - m0n);
            c[j].y = __expf(c[j].y - m0n);
            c[j].z = __expf(c[j].z - m1n);
            c[j].w = __expf(c[j].w - m1n);
            rs0 += c[j].x + c[j].y;
            rs1 += c[j].z + c[j].w;
        }
#pragma unroll
        for (int off = 1; off <= 2; off <<= 1) {
            rs0 += __shfl_xor_sync(0xffffffffu, rs0, off);
            rs1 += __shfl_xor_sync(0xffffffffu, rs1, off);
        }
        l0 = l0 * corr0 + rs0;  m0 = m0n;
        l1 = l1 * corr1 + rs1;  m1 = m1n;

#pragma unroll
        for (int j = 0; j < 16; j++) {
            o[j].x *= corr0; o[j].y *= corr0;
            o[j].z *= corr1; o[j].w *= corr1;
        }

        // ---- store P into A-layout smem (warp-private rows) ----
        {
            const int r3 = rl & 3;   // (rl+8)&3 identical
#pragma unroll
            for (int j = 0; j < 8; j++) {
                int cx = 8 * j + 2 * t;
                int cy = cx + 1;
                int bx = (cx >> 4) * 1028 + (((cx & 3) ^ r3) << 2) + ((cx >> 2) & 3);
                int by = (cy >> 4) * 1028 + (((cy & 3) ^ r3) << 2) + ((cy >> 2) & 3);
                Ps[bx + rl * 16]       = to_tf32(c[j].x);
                Ps[by + rl * 16]       = to_tf32(c[j].y);
                Ps[bx + (rl + 8) * 16] = to_tf32(c[j].z);
                Ps[by + (rl + 8) * 16] = to_tf32(c[j].w);
            }
        }
        __syncwarp();

        // ---- O += P @ V  (warp: m16 x n128 x k64) ----
#pragma unroll
        for (int kc = 0; kc < 4; kc++) {
            float4 aL = Ps4[kc * 257 + rl * 4 + sw];
            float4 aH = Ps4[kc * 257 + (rl + 8) * 4 + sw];
            uint32_t x0 = f2u(aL.x), x1 = f2u(aH.x), x2 = f2u(aL.y), x3 = f2u(aH.y);
            uint32_t z0 = f2u(aL.z), z1 = f2u(aH.z), z2 = f2u(aL.w), z3 = f2u(aH.w);
#pragma unroll
            for (int j = 0; j < 16; j++) {
                float4 bv = Vs4[kc * 516 + (8 * j + g) * 4 + sw];
                mma_tf32(o[j], x0, x1, x2, x3, f2u(bv.x), f2u(bv.y));
                mma_tf32(o[j], z0, z1, z2, z3, f2u(bv.z), f2u(bv.w));
            }
        }
    }

    // ---- epilogue ----
    float i0 = 1.0f / l0, i1 = 1.0f / l1;
    float* Obase = Og + (size_t)b * T_ * QCOLS + h * HD;
    const int rA = q0 + rl, rB = rA + 8;
#pragma unroll
    for (int j = 0; j < 16; j++) {
        int col = 8 * j + 2 * t;
        *(float2*)(Obase + (size_t)rA * QCOLS + col) = make_float2(o[j].x * i0, o[j].y * i0);
        *(float2*)(Obase + (size_t)rB * QCOLS + col) = make_float2(o[j].z * i1, o[j].w * i1);
    }
}

// ---------------------------------------------------------------------------
// Launch
// ---------------------------------------------------------------------------
extern "C" void kernel_launch(void* const* d_in, const int* in_sizes, int n_in,
                              void* d_out, int out_size)
{
    const float* x  = (const float*)d_in[0];
    const float* wq = (const float*)d_in[1];
    const float* wk = (const float*)d_in[2];
    const float* wv = (const float*)d_in[3];
    const float* wo = (const float*)d_in[4];
    float* out = (float*)d_out;

    float *q, *k, *v, *att;
    cudaGetSymbolAddress((void**)&q,   g_q);
    cudaGetSymbolAddress((void**)&k,   g_k);
    cudaGetSymbolAddress((void**)&v,   g_v);
    cudaGetSymbolAddress((void**)&att, g_att);

    cudaFuncSetAttribute(flash_tf32,
                         cudaFuncAttributeMaxDynamicSharedMemorySize, FLASH_SMEM);

    dim3 blk(256);

    init_invf_kernel<<<1, 64>>>();

    gemm_tf32<<<dim3(QCOLS  / BN, M_TOK / BM), blk>>>(x, wq, q, D_, QCOLS);
    gemm_tf32<<<dim3(KVCOLS / BN, M_TOK / BM), blk>>>(x, wk, k, D_, KVCOLS);
    gemm_tf32<<<dim3(KVCOLS / BN, M_TOK / BM), blk>>>(x, wv, v, D_, KVCOLS);

    int total_pairs = M_TOK * (NH + NKV) * (HD / 2);
    rope_kernel<<<(total_pairs + 255) / 256, 256>>>(q, k);

    flash_tf32<<<dim3(T_ / 64, NH, B_), 128, FLASH_SMEM>>>(q, k, v, att);

    gemm_tf32<<<dim3(D_ / BN, M_TOK / BM), blk>>>(att, wo, out, QCOLS, D_);
}

// round 9
// speedup vs baseline: 6.3383x; 2.2473x over previous
#include <cuda_runtime.h>
#include <math.h>
#include <stdint.h>

// ---------------------------------------------------------------------------
// Problem constants
// ---------------------------------------------------------------------------
#define B_      2
#define T_      2048
#define D_      2048
#define NH      16
#define NKV     4
#define HD      128
#define M_TOK   (B_ * T_)          // 4096
#define QCOLS   (NH * HD)          // 2048
#define KVCOLS  (NKV * HD)         // 512

// ---------------------------------------------------------------------------
// Scratch
// ---------------------------------------------------------------------------
__device__ float g_q  [M_TOK * QCOLS];
__device__ float g_k  [M_TOK * KVCOLS];
__device__ float g_v  [M_TOK * KVCOLS];
__device__ float g_att[M_TOK * QCOLS];
__device__ float g_invf[64];
// MMA-ready packed operands (tf32-rounded, tile-permuted)
__device__ float g_xp  [M_TOK * D_];
__device__ float g_attp[M_TOK * QCOLS];
__device__ float g_wqp [D_ * QCOLS];
__device__ float g_wkp [D_ * KVCOLS];
__device__ float g_wvp [D_ * KVCOLS];
__device__ float g_wop [QCOLS * D_];

// ---------------------------------------------------------------------------
// helpers
// ---------------------------------------------------------------------------
__device__ __forceinline__ float to_tf32(float x) {
    uint32_t u;
    asm("cvt.rna.tf32.f32 %0, %1;" : "=r"(u) : "f"(x));
    return __uint_as_float(u);
}
__device__ __forceinline__ uint32_t f2u(float x) { return __float_as_uint(x); }

__device__ __forceinline__ uint32_t smem_u32(const void* p) {
    uint32_t a;
    asm("{ .reg .u64 t; cvta.to.shared.u64 t, %1; cvt.u32.u64 %0, t; }"
        : "=r"(a) : "l"(p));
    return a;
}
__device__ __forceinline__ void cp16(uint32_t dst, const void* src) {
    asm volatile("cp.async.cg.shared.global [%0], [%1], 16;"
                 :: "r"(dst), "l"(src) : "memory");
}
#define CP_COMMIT() asm volatile("cp.async.commit_group;" ::: "memory")
#define CP_WAIT1()  asm volatile("cp.async.wait_group 1;" ::: "memory")
#define CP_WAIT0()  asm volatile("cp.async.wait_group 0;" ::: "memory")

__device__ __forceinline__ void mma_tf32(float4& d,
    uint32_t a0, uint32_t a1, uint32_t a2, uint32_t a3,
    uint32_t b0, uint32_t b1)
{
    asm volatile(
        "mma.sync.aligned.m16n8k8.row.col.f32.tf32.tf32.f32 "
        "{%0,%1,%2,%3}, {%4,%5,%6,%7}, {%8,%9}, {%0,%1,%2,%3};"
        : "+f"(d.x), "+f"(d.y), "+f"(d.z), "+f"(d.w)
        : "r"(a0), "r"(a1), "r"(a2), "r"(a3), "r"(b0), "r"(b1));
}

// ===========================================================================
// Pack kernels: build tf32-rounded, fragment-permuted tiles in gmem so the
// GEMM mainloop is a pure identity cp.async. Tile = 128 rows x 16 k (2048
// floats, 8KB). Intra-tile pos(r,c) = r*16 + 4*((c&3)^(r&3)) + (c>>2) — the
// exact smem image the R5-validated fragment loader expects.
// ===========================================================================

// Activations: src [M x K] row-major. grid (K/16, M/128), 256 threads.
__global__ void pack_act(const float* __restrict__ src, float* __restrict__ dst,
                         int K)
{
    __shared__ __align__(16) float tile[128 * 16];
    const int bk = blockIdx.x, bm = blockIdx.y, tid = threadIdx.x;

#pragma unroll
    for (int it = 0; it < 2; it++) {
        int idx = tid + (it << 8);          // float4 id 0..511
        int r = idx >> 2, aqi = idx & 3;
        float4 v = *(const float4*)(src + (size_t)(bm * 128 + r) * K
                                        + bk * 16 + (aqi << 2));
        tile[r * 16 + (aqi << 2) + 0] = to_tf32(v.x);
        tile[r * 16 + (aqi << 2) + 1] = to_tf32(v.y);
        tile[r * 16 + (aqi << 2) + 2] = to_tf32(v.z);
        tile[r * 16 + (aqi << 2) + 3] = to_tf32(v.w);
    }
    __syncthreads();

    float* dt = dst + ((size_t)bm * (K >> 4) + bk) * 2048;
#pragma unroll
    for (int it = 0; it < 2; it++) {
        int f = tid + (it << 8);
        int r = f >> 2, s = f & 3;
        int x0 = s ^ (r & 3);               // source col group for this slot
        float4 o = make_float4(tile[r * 16 + x0],
                               tile[r * 16 + 4 + x0],
                               tile[r * 16 + 8 + x0],
                               tile[r * 16 + 12 + x0]);
        *(float4*)(dt + (size_t)f * 4) = o;
    }
}

// Weights: src w [K x N] row-major; packs transposed (tile row = n-col of w).
// grid (K/16, N/128), 256 threads.
__global__ void pack_wgt(const float* __restrict__ w, float* __restrict__ dst,
                         int N, int K)
{
    __shared__ __align__(16) float tile[128 * 16];
    const int bk = blockIdx.x, bn = blockIdx.y, tid = threadIdx.x;

#pragma unroll
    for (int it = 0; it < 8; it++) {
        int idx = tid + (it << 8);          // scalar id 0..2047
        int c = idx >> 7, r = idx & 127;
        tile[r * 16 + c] =
            to_tf32(w[(size_t)(bk * 16 + c) * N + bn * 128 + r]);
    }
    __syncthreads();

    float* dt = dst + ((size_t)bn * (K >> 4) + bk) * 2048;
#pragma unroll
    for (int it = 0; it < 2; it++) {
        int f = tid + (it << 8);
        int r = f >> 2, s = f & 3;
        int x0 = s ^ (r & 3);
        float4 o = make_float4(tile[r * 16 + x0],
                               tile[r * 16 + 4 + x0],
                               tile[r * 16 + 8 + x0],
                               tile[r * 16 + 12 + x0]);
        *(float4*)(dt + (size_t)f * 4) = o;
    }
}

// ===========================================================================
// cp.async TF32 GEMM on packed operands. Block tile 128x128, 8 warps (4x2),
// warp tile 32x64, k16 chunks, 3-stage cp.async ring (48KB static smem).
// Mainloop: 4 identity cp16/thread + the R5-validated fragment/mma sequence.
// mode 0: fused QKV (bx<16 -> q, 16..19 -> k, 20..23 -> v); mode 1: N=2048.
// ===========================================================================
__global__ __launch_bounds__(256) void gemm_cp(
    const float* __restrict__ Ap,
    const float* __restrict__ w0, const float* __restrict__ w1,
    const float* __restrict__ w2,
    float* __restrict__ c0p, float* __restrict__ c1p, float* __restrict__ c2p,
    int K, int mode)
{
    __shared__ __align__(16) float sm[3 * 2048 * 2];   // 49152 B
    float* AsF = sm;            // 3 x 2048
    float* BsF = sm + 6144;     // 3 x 2048

    const int tid  = threadIdx.x;
    const int lane = tid & 31;
    const int wid  = tid >> 5;
    const int g    = lane >> 2;
    const int t    = lane & 3;
    const int wrow = wid & 3;
    const int wcol = wid >> 2;
    const int sw4  = t ^ (g & 3);

    const float* Wp; float* C; int Ncols, bn;
    const int bx = blockIdx.x;
    if (mode == 0) {
        if (bx < 16)      { Wp = w0; C = c0p; Ncols = 2048; bn = bx; }
        else if (bx < 20) { Wp = w1; C = c1p; Ncols = 512;  bn = bx - 16; }
        else              { Wp = w2; C = c2p; Ncols = 512;  bn = bx - 20; }
    } else { Wp = w0; C = c0p; Ncols = 2048; bn = bx; }
    const int bm  = blockIdx.y;
    const int nkt = K >> 4;

    const float* Abase = Ap + (size_t)bm * nkt * 2048;
    const float* Bbase = Wp + (size_t)bn * nkt * 2048;
    const uint32_t sA = smem_u32(AsF), sB = smem_u32(BsF);

    float4 c[2][8];
#pragma unroll
    for (int i = 0; i < 2; i++)
#pragma unroll
        for (int j = 0; j < 8; j++) c[i][j] = make_float4(0.f, 0.f, 0.f, 0.f);

    // ---- prologue: stages 0,1 ----
#pragma unroll
    for (int s = 0; s < 2; s++) {
        const float* at = Abase + (size_t)s * 2048;
        const float* bt = Bbase + (size_t)s * 2048;
#pragma unroll
        for (int it = 0; it < 2; it++) {
            int f = tid + (it << 8);
            cp16(sA + (uint32_t)(s * 2048 + f * 4) * 4, at + (size_t)f * 4);
            cp16(sB + (uint32_t)(s * 2048 + f * 4) * 4, bt + (size_t)f * 4);
        }
        CP_COMMIT();
    }

    for (int kb = 0; kb < nkt; kb++) {
        CP_WAIT1();              // slot kb landed (<=1 newer group pending)
        __syncthreads();         // all warps done with slot (kb-1) compute

        const int ns = kb + 2;
        if (ns < nkt) {
            const int slot = ns % 3;
            const float* at = Abase + (size_t)ns * 2048;
            const float* bt = Bbase + (size_t)ns * 2048;
#pragma unroll
            for (int it = 0; it < 2; it++) {
                int f = tid + (it << 8);
                cp16(sA + (uint32_t)(slot * 2048 + f * 4) * 4, at + (size_t)f * 4);
                cp16(sB + (uint32_t)(slot * 2048 + f * 4) * 4, bt + (size_t)f * 4);
            }
        }
        CP_COMMIT();             // always commit to keep group accounting

        const float4* As4 = (const float4*)(AsF + (kb % 3) * 2048);
        const float4* Bs4 = (const float4*)(BsF + (kb % 3) * 2048);

        float4 afl[2], afh[2], bf[8];
#pragma unroll
        for (int i = 0; i < 2; i++) {
            int rl = wrow * 32 + i * 16 + g;
            afl[i] = As4[rl * 4 + sw4];
            afh[i] = As4[(rl + 8) * 4 + sw4];
        }
#pragma unroll
        for (int j = 0; j < 8; j++)
            bf[j] = Bs4[(wcol * 64 + j * 8 + g) * 4 + sw4];

#pragma unroll
        for (int i = 0; i < 2; i++) {
            uint32_t a0 = f2u(afl[i].x), a1 = f2u(afh[i].x);
            uint32_t a2 = f2u(afl[i].y), a3 = f2u(afh[i].y);
#pragma unroll
            for (int j = 0; j < 8; j++)
                mma_tf32(c[i][j], a0, a1, a2, a3, f2u(bf[j].x), f2u(bf[j].y));
        }
#pragma unroll
        for (int i = 0; i < 2; i++) {
            uint32_t a0 = f2u(afl[i].z), a1 = f2u(afh[i].z);
            uint32_t a2 = f2u(afl[i].w), a3 = f2u(afh[i].w);
#pragma unroll
            for (int j = 0; j < 8; j++)
                mma_tf32(c[i][j], a0, a1, a2, a3, f2u(bf[j].z), f2u(bf[j].w));
        }
    }
    CP_WAIT0();

    // ---- epilogue (register -> gmem, R5 layout) ----
    const int row0 = bm * 128, col0 = bn * 128;
#pragma unroll
    for (int i = 0; i < 2; i++) {
        int r = row0 + wrow * 32 + i * 16 + g;
#pragma unroll
        for (int j = 0; j < 8; j++) {
            int cc = col0 + wcol * 64 + j * 8 + 2 * t;
            *(float2*)(C + (size_t)r * Ncols + cc)       = make_float2(c[i][j].x, c[i][j].y);
            *(float2*)(C + (size_t)(r + 8) * Ncols + cc) = make_float2(c[i][j].z, c[i][j].w);
        }
    }
}

// ---------------------------------------------------------------------------
// RoPE
// ---------------------------------------------------------------------------
__global__ void init_invf_kernel()
{
    int i = threadIdx.x;
    if (i < 64)
        g_invf[i] = (float)(1.0 / pow(1.0e6, (double)i / 64.0));
}

__global__ void rope_kernel(float* __restrict__ q, float* __restrict__ k)
{
    const int PPT = (NH + NKV) * (HD / 2);   // 1280
    int idx = blockIdx.x * blockDim.x + threadIdx.x;
    if (idx >= M_TOK * PPT) return;

    int m    = idx / PPT;
    int r    = idx - m * PPT;
    int head = r >> 6;
    int i    = r & 63;
    int t    = m & (T_ - 1);

    float ang = (float)t * g_invf[i];
    float s, c;
    sincosf(ang, &s, &c);

    float* base = (head < NH)
        ? (q + (size_t)m * QCOLS + head * HD)
        : (k + (size_t)m * KVCOLS + (head - NH) * HD);

    float u1 = base[i];
    float u2 = base[i + 64];
    base[i]      = u1 * c - u2 * s;
    base[i + 64] = u2 * c + u1 * s;
}

// ===========================================================================
// TF32 mma.sync flash attention (byte-identical to the R5 PASSING kernel)
// ===========================================================================
#define QS_F   (8 * 1028)
#define KS_F   (8 * 1028)
#define VS_F   (4 * 2064)
#define PS_F   (4 * 1028)
#define FLASH_SMEM ((QS_F + KS_F + VS_F + PS_F) * (int)sizeof(float))  // 115264 B

__global__ __launch_bounds__(128, 1) void flash_tf32(
    const float* __restrict__ Qg, const float* __restrict__ Kg,
    const float* __restrict__ Vg, float* __restrict__ Og)
{
    extern __shared__ float smf[];
    float* Qs = smf;
    float* Ks = Qs + QS_F;
    float* Vs = Ks + KS_F;
    float* Ps = Vs + VS_F;
    const float4* Qs4 = (const float4*)Qs;
    const float4* Ks4 = (const float4*)Ks;
    const float4* Vs4 = (const float4*)Vs;
    const float4* Ps4 = (const float4*)Ps;

    const int tid  = threadIdx.x;
    const int lane = tid & 31;
    const int wid  = tid >> 5;
    const int g    = lane >> 2;
    const int t    = lane & 3;
    const int sw   = t ^ (g & 3);
    const int qb   = blockIdx.x;
    const int h    = blockIdx.y;
    const int b    = blockIdx.z;
    const int kvh  = h >> 2;
    const int q0   = qb * 64;
    const int rl   = wid * 16 + g;
    const float scale = 0.08838834764831845f;

    const float* Qbase = Qg + (size_t)b * T_ * QCOLS  + h   * HD;
    const float* Kbase = Kg + (size_t)b * T_ * KVCOLS + kvh * HD;
    const float* Vbase = Vg + (size_t)b * T_ * KVCOLS + kvh * HD;

    for (int l = tid; l < 2048; l += 128) {
        int r  = l >> 5;
        int d4 = (l & 31) << 2;
        float4 v = *(const float4*)(Qbase + (size_t)(q0 + r) * QCOLS + d4);
        int base = (d4 >> 4) * 1028 + r * 16 + ((d4 >> 2) & 3);
        int r3 = r & 3;
        Qs[base + ((0 ^ r3) << 2)] = to_tf32(v.x);
        Qs[base + ((1 ^ r3) << 2)] = to_tf32(v.y);
        Qs[base + ((2 ^ r3) << 2)] = to_tf32(v.z);
        Qs[base + ((3 ^ r3) << 2)] = to_tf32(v.w);
    }

    float4 o[16];
#pragma unroll
    for (int j = 0; j < 16; j++) o[j] = make_float4(0.f, 0.f, 0.f, 0.f);
    float m0 = -1e30f, m1 = -1e30f, l0 = 0.f, l1 = 0.f;

    for (int kt = 0; kt <= qb; kt++) {
        __syncthreads();
        const int s0 = kt * 64;

        for (int l = tid; l < 2048; l += 128) {
            int s  = l >> 5;
            int d4 = (l & 31) << 2;
            float4 v = *(const float4*)(Kbase + (size_t)(s0 + s) * KVCOLS + d4);
            int base = (d4 >> 4) * 1028 + s * 16 + ((d4 >> 2) & 3);
            int s3 = s & 3;
            Ks[base + ((0 ^ s3) << 2)] = to_tf32(v.x);
            Ks[base + ((1 ^ s3) << 2)] = to_tf32(v.y);
            Ks[base + ((2 ^ s3) << 2)] = to_tf32(v.z);
            Ks[base + ((3 ^ s3) << 2)] = to_tf32(v.w);
        }
        for (int l = tid; l < 2048; l += 128) {
            int s  = l & 63;
            int d4 = (l >> 6) << 2;
            float4 v = *(const float4*)(Vbase + (size_t)(s0 + s) * KVCOLS + d4);
            int s3 = s & 3;
            int cb = (s >> 4) * 2064 + ((s >> 2) & 3);
            Vs[cb + (d4 + 0) * 16 + ((s3 ^ 0) << 2)] = to_tf32(v.x);
            Vs[cb + (d4 + 1) * 16 + ((s3 ^ 1) << 2)] = to_tf32(v.y);
            Vs[cb + (d4 + 2) * 16 + ((s3 ^ 2) << 2)] = to_tf32(v.z);
            Vs[cb + (d4 + 3) * 16 + ((s3 ^ 3) << 2)] = to_tf32(v.w);
        }
        __syncthreads();

        float4 c[8];
#pragma unroll
        for (int j = 0; j < 8; j++) c[j] = make_float4(0.f, 0.f, 0.f, 0.f);

#pragma unroll
        for (int kc = 0; kc < 8; kc++) {
            float4 aL = Qs4[kc * 257 + rl * 4 + sw];
            float4 aH = Qs4[kc * 257 + (rl + 8) * 4 + sw];
            uint32_t x0 = f2u(aL.x), x1 = f2u(aH.x), x2 = f2u(aL.y), x3 = f2u(aH.y);
            uint32_t z0 = f2u(aL.z), z1 = f2u(aH.z), z2 = f2u(aL.w), z3 = f2u(aH.w);
#pragma unroll
            for (int j = 0; j < 8; j++) {
                float4 bv = Ks4[kc * 257 + (8 * j + g) * 4 + sw];
                mma_tf32(c[j], x0, x1, x2, x3, f2u(bv.x), f2u(bv.y));
                mma_tf32(c[j], z0, z1, z2, z3, f2u(bv.z), f2u(bv.w));
            }
        }

#pragma unroll
        for (int j = 0; j < 8; j++) {
            c[j].x *= scale; c[j].y *= scale; c[j].z *= scale; c[j].w *= scale;
        }

        if (kt == qb) {
            const int row_lo = q0 + rl, row_hi = row_lo + 8;
#pragma unroll
            for (int j = 0; j < 8; j++) {
                int col = s0 + 8 * j + 2 * t;
                if (col     > row_lo) c[j].x = -1e30f;
                if (col + 1 > row_lo) c[j].y = -1e30f;
                if (col     > row_hi) c[j].z = -1e30f;
                if (col + 1 > row_hi) c[j].w = -1e30f;
            }
        }

        float mt0 = -1e30f, mt1 = -1e30f;
#pragma unroll
        for (int j = 0; j < 8; j++) {
            mt0 = fmaxf(mt0, fmaxf(c[j].x, c[j].y));
            mt1 = fmaxf(mt1, fmaxf(c[j].z, c[j].w));
        }
#pragma unroll
        for (int off = 1; off <= 2; off <<= 1) {
            mt0 = fmaxf(mt0, __shfl_xor_sync(0xffffffffu, mt0, off));
            mt1 = fmaxf(mt1, __shfl_xor_sync(0xffffffffu, mt1, off));
        }
        float m0n = fmaxf(m0, mt0), m1n = fmaxf(m1, mt1);
        float corr0 = __expf(m0 - m0n), corr1 = __expf(m1 - m1n);

        float rs0 = 0.f, rs1 = 0.f;
#pragma unroll
        for (int j = 0; j < 8; j++) {
            c[j].x = __expf(c[j].x - m0n);
            c[j].y = __expf(c[j].y - m0n);
            c[j].z = __expf(c[j].z - m1n);
            c[j].w = __expf(c[j].w - m1n);
            rs0 += c[j].x + c[j].y;
            rs1 += c[j].z + c[j].w;
        }
#pragma unroll
        for (int off = 1; off <= 2; off <<= 1) {
            rs0 += __shfl_xor_sync(0xffffffffu, rs0, off);
            rs1 += __shfl_xor_sync(0xffffffffu, rs1, off);
        }
        l0 = l0 * corr0 + rs0;  m0 = m0n;
        l1 = l1 * corr1 + rs1;  m1 = m1n;

#pragma unroll
        for (int j = 0; j < 16; j++) {
            o[j].x *= corr0; o[j].y *= corr0;
            o[j].z *= corr1; o[j].w *= corr1;
        }

        {
            const int r3 = rl & 3;
#pragma unroll
            for (int j = 0; j < 8; j++) {
                int cx = 8 * j + 2 * t;
                int cy = cx + 1;
                int bx = (cx >> 4) * 1028 + (((cx & 3) ^ r3) << 2) + ((cx >> 2) & 3);
                int by = (cy >> 4) * 1028 + (((cy & 3) ^ r3) << 2) + ((cy >> 2) & 3);
                Ps[bx + rl * 16]       = to_tf32(c[j].x);
                Ps[by + rl * 16]       = to_tf32(c[j].y);
                Ps[bx + (rl + 8) * 16] = to_tf32(c[j].z);
                Ps[by + (rl + 8) * 16] = to_tf32(c[j].w);
            }
        }
        __syncwarp();

#pragma unroll
        for (int kc = 0; kc < 4; kc++) {
            float4 aL = Ps4[kc * 257 + rl * 4 + sw];
            float4 aH = Ps4[kc * 257 + (rl + 8) * 4 + sw];
            uint32_t x0 = f2u(aL.x), x1 = f2u(aH.x), x2 = f2u(aL.y), x3 = f2u(aH.y);
            uint32_t z0 = f2u(aL.z), z1 = f2u(aH.z), z2 = f2u(aL.w), z3 = f2u(aH.w);
#pragma unroll
            for (int j = 0; j < 16; j++) {
                float4 bv = Vs4[kc * 516 + (8 * j + g) * 4 + sw];
                mma_tf32(o[j], x0, x1, x2, x3, f2u(bv.x), f2u(bv.y));
                mma_tf32(o[j], z0, z1, z2, z3, f2u(bv.z), f2u(bv.w));
            }
        }
    }

    float i0 = 1.0f / l0, i1 = 1.0f / l1;
    float* Obase = Og + (size_t)b * T_ * QCOLS + h * HD;
    const int rA = q0 + rl, rB = rA + 8;
#pragma unroll
    for (int j = 0; j < 16; j++) {
        int col = 8 * j + 2 * t;
        *(float2*)(Obase + (size_t)rA * QCOLS + col) = make_float2(o[j].x * i0, o[j].y * i0);
        *(float2*)(Obase + (size_t)rB * QCOLS + col) = make_float2(o[j].z * i1, o[j].w * i1);
    }
}

// ---------------------------------------------------------------------------
// Launch
// ---------------------------------------------------------------------------
extern "C" void kernel_launch(void* const* d_in, const int* in_sizes, int n_in,
                              void* d_out, int out_size)
{
    const float* x  = (const float*)d_in[0];
    const float* wq = (const float*)d_in[1];
    const float* wk = (const float*)d_in[2];
    const float* wv = (const float*)d_in[3];
    const float* wo = (const float*)d_in[4];
    float* out = (float*)d_out;

    float *q, *k, *v, *att, *xp, *attp, *wqp, *wkp, *wvp, *wop;
    cudaGetSymbolAddress((void**)&q,    g_q);
    cudaGetSymbolAddress((void**)&k,    g_k);
    cudaGetSymbolAddress((void**)&v,    g_v);
    cudaGetSymbolAddress((void**)&att,  g_att);
    cudaGetSymbolAddress((void**)&xp,   g_xp);
    cudaGetSymbolAddress((void**)&attp, g_attp);
    cudaGetSymbolAddress((void**)&wqp,  g_wqp);
    cudaGetSymbolAddress((void**)&wkp,  g_wkp);
    cudaGetSymbolAddress((void**)&wvp,  g_wvp);
    cudaGetSymbolAddress((void**)&wop,  g_wop);

    cudaFuncSetAttribute(flash_tf32,
                         cudaFuncAttributeMaxDynamicSharedMemorySize, FLASH_SMEM);

    init_invf_kernel<<<1, 64>>>();

    // Pack operands into MMA-ready tiles (round + permute once)
    pack_act<<<dim3(D_ / 16, M_TOK / 128), 256>>>(x, xp, D_);
    pack_wgt<<<dim3(D_ / 16, QCOLS  / 128), 256>>>(wq, wqp, QCOLS,  D_);
    pack_wgt<<<dim3(D_ / 16, KVCOLS / 128), 256>>>(wk, wkp, KVCOLS, D_);
    pack_wgt<<<dim3(D_ / 16, KVCOLS / 128), 256>>>(wv, wvp, KVCOLS, D_);
    pack_wgt<<<dim3(QCOLS / 16, D_ / 128), 256>>>(wo, wop, D_, QCOLS);

    // Fused QKV projection
    gemm_cp<<<dim3(24, 32), 256>>>(xp, wqp, wkp, wvp, q, k, v, D_, 0);

    // RoPE
    int total_pairs = M_TOK * (NH + NKV) * (HD / 2);
    rope_kernel<<<(total_pairs + 255) / 256, 256>>>(q, k);

    // Causal GQA flash attention
    flash_tf32<<<dim3(T_ / 64, NH, B_), 128, FLASH_SMEM>>>(q, k, v, att);

    // Output projection
    pack_act<<<dim3(QCOLS / 16, M_TOK / 128), 256>>>(att, attp, QCOLS);
    gemm_cp<<<dim3(16, 32), 256>>>(attp, wop, nullptr, nullptr,
                                   out, nullptr, nullptr, QCOLS, 1);
}

// round 12
// speedup vs baseline: 6.6223x; 1.0448x over previous
#include <cuda_runtime.h>
#include <math.h>
#include <stdint.h>

// ---------------------------------------------------------------------------
// Problem constants
// ---------------------------------------------------------------------------
#define B_      2
#define T_      2048
#define D_      2048
#define NH      16
#define NKV     4
#define HD      128
#define M_TOK   (B_ * T_)          // 4096
#define QCOLS   (NH * HD)          // 2048
#define KVCOLS  (NKV * HD)         // 512

// ---------------------------------------------------------------------------
// Scratch
// ---------------------------------------------------------------------------
__device__ float g_q  [M_TOK * QCOLS];
__device__ float g_k  [M_TOK * KVCOLS];
__device__ float g_v  [M_TOK * KVCOLS];
__device__ float g_att[M_TOK * QCOLS];
__device__ float g_invf[64];
// MMA-ready packed operands (tf32-rounded, tile-permuted)
__device__ float g_xp  [M_TOK * D_];
__device__ float g_attp[M_TOK * QCOLS];
__device__ float g_wqp [D_ * QCOLS];
__device__ float g_wkp [D_ * KVCOLS];
__device__ float g_wvp [D_ * KVCOLS];
__device__ float g_wop [QCOLS * D_];

// ---------------------------------------------------------------------------
// helpers
// ---------------------------------------------------------------------------
__device__ __forceinline__ float to_tf32(float x) {
    uint32_t u;
    asm("cvt.rna.tf32.f32 %0, %1;" : "=r"(u) : "f"(x));
    return __uint_as_float(u);
}
__device__ __forceinline__ uint32_t f2u(float x) { return __float_as_uint(x); }

__device__ __forceinline__ uint32_t smem_u32(const void* p) {
    uint32_t a;
    asm("{ .reg .u64 t; cvta.to.shared.u64 t, %1; cvt.u32.u64 %0, t; }"
        : "=r"(a) : "l"(p));
    return a;
}
__device__ __forceinline__ void cp16(uint32_t dst, const void* src) {
    asm volatile("cp.async.cg.shared.global [%0], [%1], 16;"
                 :: "r"(dst), "l"(src) : "memory");
}
#define CP_COMMIT() asm volatile("cp.async.commit_group;" ::: "memory")
#define CP_WAIT1()  asm volatile("cp.async.wait_group 1;" ::: "memory")
#define CP_WAIT0()  asm volatile("cp.async.wait_group 0;" ::: "memory")

__device__ __forceinline__ void mma_tf32(float4& d,
    uint32_t a0, uint32_t a1, uint32_t a2, uint32_t a3,
    uint32_t b0, uint32_t b1)
{
    asm volatile(
        "mma.sync.aligned.m16n8k8.row.col.f32.tf32.tf32.f32 "
        "{%0,%1,%2,%3}, {%4,%5,%6,%7}, {%8,%9}, {%0,%1,%2,%3};"
        : "+f"(d.x), "+f"(d.y), "+f"(d.z), "+f"(d.w)
        : "r"(a0), "r"(a1), "r"(a2), "r"(a3), "r"(b0), "r"(b1));
}

// ===========================================================================
// Pack kernels (unchanged from R8 — validated)
// ===========================================================================
__global__ void pack_act(const float* __restrict__ src, float* __restrict__ dst,
                         int K)
{
    __shared__ __align__(16) float tile[128 * 16];
    const int bk = blockIdx.x, bm = blockIdx.y, tid = threadIdx.x;

#pragma unroll
    for (int it = 0; it < 2; it++) {
        int idx = tid + (it << 8);
        int r = idx >> 2, aqi = idx & 3;
        float4 v = *(const float4*)(src + (size_t)(bm * 128 + r) * K
                                        + bk * 16 + (aqi << 2));
        tile[r * 16 + (aqi << 2) + 0] = to_tf32(v.x);
        tile[r * 16 + (aqi << 2) + 1] = to_tf32(v.y);
        tile[r * 16 + (aqi << 2) + 2] = to_tf32(v.z);
        tile[r * 16 + (aqi << 2) + 3] = to_tf32(v.w);
    }
    __syncthreads();

    float* dt = dst + ((size_t)bm * (K >> 4) + bk) * 2048;
#pragma unroll
    for (int it = 0; it < 2; it++) {
        int f = tid + (it << 8);
        int r = f >> 2, s = f & 3;
        int x0 = s ^ (r & 3);
        float4 o = make_float4(tile[r * 16 + x0],
                               tile[r * 16 + 4 + x0],
                               tile[r * 16 + 8 + x0],
                               tile[r * 16 + 12 + x0]);
        *(float4*)(dt + (size_t)f * 4) = o;
    }
}

__global__ void pack_wgt(const float* __restrict__ w, float* __restrict__ dst,
                         int N, int K)
{
    __shared__ __align__(16) float tile[128 * 16];
    const int bk = blockIdx.x, bn = blockIdx.y, tid = threadIdx.x;

#pragma unroll
    for (int it = 0; it < 8; it++) {
        int idx = tid + (it << 8);
        int c = idx >> 7, r = idx & 127;
        tile[r * 16 + c] =
            to_tf32(w[(size_t)(bk * 16 + c) * N + bn * 128 + r]);
    }
    __syncthreads();

    float* dt = dst + ((size_t)bn * (K >> 4) + bk) * 2048;
#pragma unroll
    for (int it = 0; it < 2; it++) {
        int f = tid + (it << 8);
        int r = f >> 2, s = f & 3;
        int x0 = s ^ (r & 3);
        float4 o = make_float4(tile[r * 16 + x0],
                               tile[r * 16 + 4 + x0],
                               tile[r * 16 + 8 + x0],
                               tile[r * 16 + 12 + x0]);
        *(float4*)(dt + (size_t)f * 4) = o;
    }
}

// ===========================================================================
// cp.async TF32 GEMM (unchanged from R8 — validated at 1217us total)
// ===========================================================================
__global__ __launch_bounds__(256) void gemm_cp(
    const float* __restrict__ Ap,
    const float* __restrict__ w0, const float* __restrict__ w1,
    const float* __restrict__ w2,
    float* __restrict__ c0p, float* __restrict__ c1p, float* __restrict__ c2p,
    int K, int mode)
{
    __shared__ __align__(16) float sm[3 * 2048 * 2];   // 49152 B
    float* AsF = sm;
    float* BsF = sm + 6144;

    const int tid  = threadIdx.x;
    const int lane = tid & 31;
    const int wid  = tid >> 5;
    const int g    = lane >> 2;
    const int t    = lane & 3;
    const int wrow = wid & 3;
    const int wcol = wid >> 2;
    const int sw4  = t ^ (g & 3);

    const float* Wp; float* C; int Ncols, bn;
    const int bx = blockIdx.x;
    if (mode == 0) {
        if (bx < 16)      { Wp = w0; C = c0p; Ncols = 2048; bn = bx; }
        else if (bx < 20) { Wp = w1; C = c1p; Ncols = 512;  bn = bx - 16; }
        else              { Wp = w2; C = c2p; Ncols = 512;  bn = bx - 20; }
    } else { Wp = w0; C = c0p; Ncols = 2048; bn = bx; }
    const int bm  = blockIdx.y;
    const int nkt = K >> 4;

    const float* Abase = Ap + (size_t)bm * nkt * 2048;
    const float* Bbase = Wp + (size_t)bn * nkt * 2048;
    const uint32_t sA = smem_u32(AsF), sB = smem_u32(BsF);

    float4 c[2][8];
#pragma unroll
    for (int i = 0; i < 2; i++)
#pragma unroll
        for (int j = 0; j < 8; j++) c[i][j] = make_float4(0.f, 0.f, 0.f, 0.f);

#pragma unroll
    for (int s = 0; s < 2; s++) {
        const float* at = Abase + (size_t)s * 2048;
        const float* bt = Bbase + (size_t)s * 2048;
#pragma unroll
        for (int it = 0; it < 2; it++) {
            int f = tid + (it << 8);
            cp16(sA + (uint32_t)(s * 2048 + f * 4) * 4, at + (size_t)f * 4);
            cp16(sB + (uint32_t)(s * 2048 + f * 4) * 4, bt + (size_t)f * 4);
        }
        CP_COMMIT();
    }

    for (int kb = 0; kb < nkt; kb++) {
        CP_WAIT1();
        __syncthreads();

        const int ns = kb + 2;
        if (ns < nkt) {
            const int slot = ns % 3;
            const float* at = Abase + (size_t)ns * 2048;
            const float* bt = Bbase + (size_t)ns * 2048;
#pragma unroll
            for (int it = 0; it < 2; it++) {
                int f = tid + (it << 8);
                cp16(sA + (uint32_t)(slot * 2048 + f * 4) * 4, at + (size_t)f * 4);
                cp16(sB + (uint32_t)(slot * 2048 + f * 4) * 4, bt + (size_t)f * 4);
            }
        }
        CP_COMMIT();

        const float4* As4 = (const float4*)(AsF + (kb % 3) * 2048);
        const float4* Bs4 = (const float4*)(BsF + (kb % 3) * 2048);

        float4 afl[2], afh[2], bf[8];
#pragma unroll
        for (int i = 0; i < 2; i++) {
            int rl = wrow * 32 + i * 16 + g;
            afl[i] = As4[rl * 4 + sw4];
            afh[i] = As4[(rl + 8) * 4 + sw4];
        }
#pragma unroll
        for (int j = 0; j < 8; j++)
            bf[j] = Bs4[(wcol * 64 + j * 8 + g) * 4 + sw4];

#pragma unroll
        for (int i = 0; i < 2; i++) {
            uint32_t a0 = f2u(afl[i].x), a1 = f2u(afh[i].x);
            uint32_t a2 = f2u(afl[i].y), a3 = f2u(afh[i].y);
#pragma unroll
            for (int j = 0; j < 8; j++)
                mma_tf32(c[i][j], a0, a1, a2, a3, f2u(bf[j].x), f2u(bf[j].y));
        }
#pragma unroll
        for (int i = 0; i < 2; i++) {
            uint32_t a0 = f2u(afl[i].z), a1 = f2u(afh[i].z);
            uint32_t a2 = f2u(afl[i].w), a3 = f2u(afh[i].w);
#pragma unroll
            for (int j = 0; j < 8; j++)
                mma_tf32(c[i][j], a0, a1, a2, a3, f2u(bf[j].z), f2u(bf[j].w));
        }
    }
    CP_WAIT0();

    const int row0 = bm * 128, col0 = bn * 128;
#pragma unroll
    for (int i = 0; i < 2; i++) {
        int r = row0 + wrow * 32 + i * 16 + g;
#pragma unroll
        for (int j = 0; j < 8; j++) {
            int cc = col0 + wcol * 64 + j * 8 + 2 * t;
            *(float2*)(C + (size_t)r * Ncols + cc)       = make_float2(c[i][j].x, c[i][j].y);
            *(float2*)(C + (size_t)(r + 8) * Ncols + cc) = make_float2(c[i][j].z, c[i][j].w);
        }
    }
}

// ---------------------------------------------------------------------------
// RoPE
// ---------------------------------------------------------------------------
__global__ void init_invf_kernel()
{
    int i = threadIdx.x;
    if (i < 64)
        g_invf[i] = (float)(1.0 / pow(1.0e6, (double)i / 64.0));
}

__global__ void rope_kernel(float* __restrict__ q, float* __restrict__ k)
{
    const int PPT = (NH + NKV) * (HD / 2);   // 1280
    int idx = blockIdx.x * blockDim.x + threadIdx.x;
    if (idx >= M_TOK * PPT) return;

    int m    = idx / PPT;
    int r    = idx - m * PPT;
    int head = r >> 6;
    int i    = r & 63;
    int t    = m & (T_ - 1);

    float ang = (float)t * g_invf[i];
    float s, c;
    sincosf(ang, &s, &c);

    float* base = (head < NH)
        ? (q + (size_t)m * QCOLS + head * HD)
        : (k + (size_t)m * KVCOLS + (head - NH) * HD);

    float u1 = base[i];
    float u2 = base[i + 64];
    base[i]      = u1 * c - u2 * s;
    base[i + 64] = u2 * c + u1 * s;
}

// ===========================================================================
// TF32 flash attention — BM=128 q rows, BN=64 kv cols, 256 threads (8 warps).
// Warp w owns q rows w*16..w*16+15. Per-row math identical to the R5/R8
// passing kernel (same K-tile sequence, same accumulation order).
// Q: 8 chunks x (128x16 + 4 pad) = 2052 floats/chunk.
// K: 8 chunks x 1028.  V: 4 chunks x 2064.  P: 4 chunks x 2052.
// smem = (8*2052 + 8*1028 + 4*2064 + 4*2052)*4 = 164416 B -> 1 CTA/SM.
// Heavy q-blocks launch first (qb reversed) for wave balance.
// ===========================================================================
#define QS_F   (8 * 2052)
#define KS_F   (8 * 1028)
#define VS_F   (4 * 2064)
#define PS_F   (4 * 2052)
#define FLASH_SMEM ((QS_F + KS_F + VS_F + PS_F) * (int)sizeof(float))  // 164416

__global__ __launch_bounds__(256, 1) void flash_tf32(
    const float* __restrict__ Qg, const float* __restrict__ Kg,
    const float* __restrict__ Vg, float* __restrict__ Og)
{
    extern __shared__ float smf[];
    float* Qs = smf;
    float* Ks = Qs + QS_F;
    float* Vs = Ks + KS_F;
    float* Ps = Vs + VS_F;
    const float4* Qs4 = (const float4*)Qs;
    const float4* Ks4 = (const float4*)Ks;
    const float4* Vs4 = (const float4*)Vs;
    const float4* Ps4 = (const float4*)Ps;

    const int tid  = threadIdx.x;
    const int lane = tid & 31;
    const int wid  = tid >> 5;
    const int g    = lane >> 2;
    const int t    = lane & 3;
    const int sw   = t ^ (g & 3);
    const int qb   = (int)gridDim.x - 1 - (int)blockIdx.x;  // heavy first
    const int h    = blockIdx.y;
    const int b    = blockIdx.z;
    const int kvh  = h >> 2;
    const int q0   = qb * 128;
    const int rl   = wid * 16 + g;          // 0..127 ; rl&3 == g&3
    const float scale = 0.08838834764831845f;

    const float* Qbase = Qg + (size_t)b * T_ * QCOLS  + h   * HD;
    const float* Kbase = Kg + (size_t)b * T_ * KVCOLS + kvh * HD;
    const float* Vbase = Vg + (size_t)b * T_ * KVCOLS + kvh * HD;

    // ---- load Q tile [128 rows][128 dims] ----
    for (int l = tid; l < 4096; l += 256) {
        int r  = l >> 5;
        int d4 = (l & 31) << 2;
        float4 v = *(const float4*)(Qbase + (size_t)(q0 + r) * QCOLS + d4);
        int base = (d4 >> 4) * 2052 + r * 16 + ((d4 >> 2) & 3);
        int r3 = r & 3;
        Qs[base + ((0 ^ r3) << 2)] = to_tf32(v.x);
        Qs[base + ((1 ^ r3) << 2)] = to_tf32(v.y);
        Qs[base + ((2 ^ r3) << 2)] = to_tf32(v.z);
        Qs[base + ((3 ^ r3) << 2)] = to_tf32(v.w);
    }

    float4 o[16];
#pragma unroll
    for (int j = 0; j < 16; j++) o[j] = make_float4(0.f, 0.f, 0.f, 0.f);
    float m0 = -1e30f, m1 = -1e30f, l0 = 0.f, l1 = 0.f;

    const int ktmax = 2 * qb + 1;
    for (int kt = 0; kt <= ktmax; kt++) {
        __syncthreads();
        const int s0 = kt * 64;

        // K tile [64 tokens][128 dims]
        for (int l = tid; l < 2048; l += 256) {
            int s  = l >> 5;
            int d4 = (l & 31) << 2;
            float4 v = *(const float4*)(Kbase + (size_t)(s0 + s) * KVCOLS + d4);
            int base = (d4 >> 4) * 1028 + s * 16 + ((d4 >> 2) & 3);
            int s3 = s & 3;
            Ks[base + ((0 ^ s3) << 2)] = to_tf32(v.x);
            Ks[base + ((1 ^ s3) << 2)] = to_tf32(v.y);
            Ks[base + ((2 ^ s3) << 2)] = to_tf32(v.z);
            Ks[base + ((3 ^ s3) << 2)] = to_tf32(v.w);
        }
        // V tile [64 tokens][128 dims] -> B-layout [dim][token]
        for (int l = tid; l < 2048; l += 256) {
            int s  = l & 63;
            int d4 = (l >> 6) << 2;
            float4 v = *(const float4*)(Vbase + (size_t)(s0 + s) * KVCOLS + d4);
            int s3 = s & 3;
            int cb = (s >> 4) * 2064 + ((s >> 2) & 3);
            Vs[cb + (d4 + 0) * 16 + ((s3 ^ 0) << 2)] = to_tf32(v.x);
            Vs[cb + (d4 + 1) * 16 + ((s3 ^ 1) << 2)] = to_tf32(v.y);
            Vs[cb + (d4 + 2) * 16 + ((s3 ^ 2) << 2)] = to_tf32(v.z);
            Vs[cb + (d4 + 3) * 16 + ((s3 ^ 3) << 2)] = to_tf32(v.w);
        }
        __syncthreads();

        // ---- S = Q @ K^T (warp: m16 x n64 x k128) ----
        float4 c[8];
#pragma unroll
        for (int j = 0; j < 8; j++) c[j] = make_float4(0.f, 0.f, 0.f, 0.f);

#pragma unroll
        for (int kc = 0; kc < 8; kc++) {
            float4 aL = Qs4[kc * 513 + rl * 4 + sw];
            float4 aH = Qs4[kc * 513 + (rl + 8) * 4 + sw];
            uint32_t x0 = f2u(aL.x), x1 = f2u(aH.x), x2 = f2u(aL.y), x3 = f2u(aH.y);
            uint32_t z0 = f2u(aL.z), z1 = f2u(aH.z), z2 = f2u(aL.w), z3 = f2u(aH.w);
#pragma unroll
            for (int j = 0; j < 8; j++) {
                float4 bv = Ks4[kc * 257 + (8 * j + g) * 4 + sw];
                mma_tf32(c[j], x0, x1, x2, x3, f2u(bv.x), f2u(bv.y));
                mma_tf32(c[j], z0, z1, z2, z3, f2u(bv.z), f2u(bv.w));
            }
        }

#pragma unroll
        for (int j = 0; j < 8; j++) {
            c[j].x *= scale; c[j].y *= scale; c[j].z *= scale; c[j].w *= scale;
        }

        if (kt >= 2 * qb) {     // diagonal-crossing tiles: mask col > row
            const int row_lo = q0 + rl, row_hi = row_lo + 8;
#pragma unroll
            for (int j = 0; j < 8; j++) {
                int col = s0 + 8 * j + 2 * t;
                if (col     > row_lo) c[j].x = -1e30f;
                if (col + 1 > row_lo) c[j].y = -1e30f;
                if (col     > row_hi) c[j].z = -1e30f;
                if (col + 1 > row_hi) c[j].w = -1e30f;
            }
        }

        // ---- online softmax ----
        float mt0 = -1e30f, mt1 = -1e30f;
#pragma unroll
        for (int j = 0; j < 8; j++) {
            mt0 = fmaxf(mt0, fmaxf(c[j].x, c[j].y));
            mt1 = fmaxf(mt1, fmaxf(c[j].z, c[j].w));
        }
#pragma unroll
        for (int off = 1; off <= 2; off <<= 1) {
            mt0 = fmaxf(mt0, __shfl_xor_sync(0xffffffffu, mt0, off));
            mt1 = fmaxf(mt1, __shfl_xor_sync(0xffffffffu, mt1, off));
        }
        float m0n = fmaxf(m0, mt0), m1n = fmaxf(m1, mt1);
        float corr0 = __expf(m0 - m0n), corr1 = __expf(m1 - m1n);

        float rs0 = 0.f, rs1 = 0.f;
#pragma unroll
        for (int j = 0; j < 8; j++) {
            c[j].x = __expf(c[j].x - m0n);
            c[j].y = __expf(c[j].y - m0n);
            c[j].z = __expf(c[j].z - m1n);
            c[j].w = __expf(c[j].w - m1n);
            rs0 += c[j].x + c[j].y;
            rs1 += c[j].z + c[j].w;
        }
#pragma unroll
        for (int off = 1; off <= 2; off <<= 1) {
            rs0 += __shfl_xor_sync(0xffffffffu, rs0, off);
            rs1 += __shfl_xor_sync(0xffffffffu, rs1, off);
        }
        l0 = l0 * corr0 + rs0;  m0 = m0n;
        l1 = l1 * corr1 + rs1;  m1 = m1n;

#pragma unroll
        for (int j = 0; j < 16; j++) {
            o[j].x *= corr0; o[j].y *= corr0;
            o[j].z *= corr1; o[j].w *= corr1;
        }

        // ---- store P (warp-private rows) ----
        {
            const int r3 = rl & 3;
#pragma unroll
            for (int j = 0; j < 8; j++) {
                int cx = 8 * j + 2 * t;
                int cy = cx + 1;
                int bx = (cx >> 4) * 2052 + (((cx & 3) ^ r3) << 2) + ((cx >> 2) & 3);
                int by = (cy >> 4) * 2052 + (((cy & 3) ^ r3) << 2) + ((cy >> 2) & 3);
                Ps[bx + rl * 16]       = to_tf32(c[j].x);
                Ps[by + rl * 16]       = to_tf32(c[j].y);
                Ps[bx + (rl + 8) * 16] = to_tf32(c[j].z);
                Ps[by + (rl + 8) * 16] = to_tf32(c[j].w);
            }
        }
        __syncwarp();

        // ---- O += P @ V (warp: m16 x n128 x k64) ----
#pragma unroll
        for (int kc = 0; kc < 4; kc++) {
            float4 aL = Ps4[kc * 513 + rl * 4 + sw];
            float4 aH = Ps4[kc * 513 + (rl + 8) * 4 + sw];
            uint32_t x0 = f2u(aL.x), x1 = f2u(aH.x), x2 = f2u(aL.y), x3 = f2u(aH.y);
            uint32_t z0 = f2u(aL.z), z1 = f2u(aH.z), z2 = f2u(aL.w), z3 = f2u(aH.w);
#pragma unroll
            for (int j = 0; j < 16; j++) {
                float4 bv = Vs4[kc * 516 + (8 * j + g) * 4 + sw];
                mma_tf32(o[j], x0, x1, x2, x3, f2u(bv.x), f2u(bv.y));
                mma_tf32(o[j], z0, z1, z2, z3, f2u(bv.z), f2u(bv.w));
            }
        }
    }

    // ---- epilogue ----
    float i0 = 1.0f / l0, i1 = 1.0f / l1;
    float* Obase = Og + (size_t)b * T_ * QCOLS + h * HD;
    const int rA = q0 + rl, rB = rA + 8;
#pragma unroll
    for (int j = 0; j < 16; j++) {
        int col = 8 * j + 2 * t;
        *(float2*)(Obase + (size_t)rA * QCOLS + col) = make_float2(o[j].x * i0, o[j].y * i0);
        *(float2*)(Obase + (size_t)rB * QCOLS + col) = make_float2(o[j].z * i1, o[j].w * i1);
    }
}

// ---------------------------------------------------------------------------
// Launch
// ---------------------------------------------------------------------------
extern "C" void kernel_launch(void* const* d_in, const int* in_sizes, int n_in,
                              void* d_out, int out_size)
{
    const float* x  = (const float*)d_in[0];
    const float* wq = (const float*)d_in[1];
    const float* wk = (const float*)d_in[2];
    const float* wv = (const float*)d_in[3];
    const float* wo = (const float*)d_in[4];
    float* out = (float*)d_out;

    float *q, *k, *v, *att, *xp, *attp, *wqp, *wkp, *wvp, *wop;
    cudaGetSymbolAddress((void**)&q,    g_q);
    cudaGetSymbolAddress((void**)&k,    g_k);
    cudaGetSymbolAddress((void**)&v,    g_v);
    cudaGetSymbolAddress((void**)&att,  g_att);
    cudaGetSymbolAddress((void**)&xp,   g_xp);
    cudaGetSymbolAddress((void**)&attp, g_attp);
    cudaGetSymbolAddress((void**)&wqp,  g_wqp);
    cudaGetSymbolAddress((void**)&wkp,  g_wkp);
    cudaGetSymbolAddress((void**)&wvp,  g_wvp);
    cudaGetSymbolAddress((void**)&wop,  g_wop);

    cudaFuncSetAttribute(flash_tf32,
                         cudaFuncAttributeMaxDynamicSharedMemorySize, FLASH_SMEM);

    init_invf_kernel<<<1, 64>>>();

    // Pack operands into MMA-ready tiles
    pack_act<<<dim3(D_ / 16, M_TOK / 128), 256>>>(x, xp, D_);
    pack_wgt<<<dim3(D_ / 16, QCOLS  / 128), 256>>>(wq, wqp, QCOLS,  D_);
    pack_wgt<<<dim3(D_ / 16, KVCOLS / 128), 256>>>(wk, wkp, KVCOLS, D_);
    pack_wgt<<<dim3(D_ / 16, KVCOLS / 128), 256>>>(wv, wvp, KVCOLS, D_);
    pack_wgt<<<dim3(QCOLS / 16, D_ / 128), 256>>>(wo, wop, D_, QCOLS);

    // Fused QKV projection
    gemm_cp<<<dim3(24, 32), 256>>>(xp, wqp, wkp, wvp, q, k, v, D_, 0);

    // RoPE
    int total_pairs = M_TOK * (NH + NKV) * (HD / 2);
    rope_kernel<<<(total_pairs + 255) / 256, 256>>>(q, k);

    // Causal GQA flash attention (BM=128)
    flash_tf32<<<dim3(T_ / 128, NH, B_), 256, FLASH_SMEM>>>(q, k, v, att);

    // Output projection
    pack_act<<<dim3(QCOLS / 16, M_TOK / 128), 256>>>(att, attp, QCOLS);
    gemm_cp<<<dim3(16, 32), 256>>>(attp, wop, nullptr, nullptr,
                                   out, nullptr, nullptr, QCOLS, 1);
}

// round 13
// speedup vs baseline: 7.4697x; 1.1280x over previous
#include <cuda_runtime.h>
#include <math.h>
#include <stdint.h>

// ---------------------------------------------------------------------------
// Problem constants
// ---------------------------------------------------------------------------
#define B_      2
#define T_      2048
#define D_      2048
#define NH      16
#define NKV     4
#define HD      128
#define M_TOK   (B_ * T_)          // 4096
#define QCOLS   (NH * HD)          // 2048
#define KVCOLS  (NKV * HD)         // 512

// ---------------------------------------------------------------------------
// Scratch
// ---------------------------------------------------------------------------
__device__ float g_q  [M_TOK * QCOLS];
__device__ float g_k  [M_TOK * KVCOLS];
__device__ float g_v  [M_TOK * KVCOLS];
__device__ float g_att[M_TOK * QCOLS];
__device__ float g_invf[64];
// MMA-ready packed operands (tf32-rounded, tile-permuted)
__device__ float g_xp  [M_TOK * D_];
__device__ float g_attp[M_TOK * QCOLS];
__device__ float g_wqp [D_ * QCOLS];
__device__ float g_wkp [D_ * KVCOLS];
__device__ float g_wvp [D_ * KVCOLS];
__device__ float g_wop [QCOLS * D_];
// flash-ready packed K/V tiles (pre-swizzled smem images, 8192 floats/tile)
__device__ float g_kp  [M_TOK * KVCOLS];
__device__ float g_vp  [M_TOK * KVCOLS];

// ---------------------------------------------------------------------------
// helpers
// ---------------------------------------------------------------------------
__device__ __forceinline__ float to_tf32(float x) {
    uint32_t u;
    asm("cvt.rna.tf32.f32 %0, %1;" : "=r"(u) : "f"(x));
    return __uint_as_float(u);
}
__device__ __forceinline__ uint32_t f2u(float x) { return __float_as_uint(x); }

__device__ __forceinline__ uint32_t smem_u32(const void* p) {
    uint32_t a;
    asm("{ .reg .u64 t; cvta.to.shared.u64 t, %1; cvt.u32.u64 %0, t; }"
        : "=r"(a) : "l"(p));
    return a;
}
__device__ __forceinline__ void cp16(uint32_t dst, const void* src) {
    asm volatile("cp.async.cg.shared.global [%0], [%1], 16;"
                 :: "r"(dst), "l"(src) : "memory");
}
#define CP_COMMIT() asm volatile("cp.async.commit_group;" ::: "memory")
#define CP_WAIT2()  asm volatile("cp.async.wait_group 2;" ::: "memory")
#define CP_WAIT1()  asm volatile("cp.async.wait_group 1;" ::: "memory")
#define CP_WAIT0()  asm volatile("cp.async.wait_group 0;" ::: "memory")

__device__ __forceinline__ void mma_tf32(float4& d,
    uint32_t a0, uint32_t a1, uint32_t a2, uint32_t a3,
    uint32_t b0, uint32_t b1)
{
    asm volatile(
        "mma.sync.aligned.m16n8k8.row.col.f32.tf32.tf32.f32 "
        "{%0,%1,%2,%3}, {%4,%5,%6,%7}, {%8,%9}, {%0,%1,%2,%3};"
        : "+f"(d.x), "+f"(d.y), "+f"(d.z), "+f"(d.w)
        : "r"(a0), "r"(a1), "r"(a2), "r"(a3), "r"(b0), "r"(b1));
}

// ===========================================================================
// Pack kernels (GEMM operands) — validated in R8. pack_act additionally
// initializes the RoPE invf table from block (0,0) (consumed only later).
// ===========================================================================
__global__ void pack_act(const float* __restrict__ src, float* __restrict__ dst,
                         int K)
{
    __shared__ __align__(16) float tile[128 * 16];
    const int bk = blockIdx.x, bm = blockIdx.y, tid = threadIdx.x;

    if (bk == 0 && bm == 0 && tid < 64)
        g_invf[tid] = (float)(1.0 / pow(1.0e6, (double)tid / 64.0));

#pragma unroll
    for (int it = 0; it < 2; it++) {
        int idx = tid + (it << 8);
        int r = idx >> 2, aqi = idx & 3;
        float4 v = *(const float4*)(src + (size_t)(bm * 128 + r) * K
                                        + bk * 16 + (aqi << 2));
        tile[r * 16 + (aqi << 2) + 0] = to_tf32(v.x);
        tile[r * 16 + (aqi << 2) + 1] = to_tf32(v.y);
        tile[r * 16 + (aqi << 2) + 2] = to_tf32(v.z);
        tile[r * 16 + (aqi << 2) + 3] = to_tf32(v.w);
    }
    __syncthreads();

    float* dt = dst + ((size_t)bm * (K >> 4) + bk) * 2048;
#pragma unroll
    for (int it = 0; it < 2; it++) {
        int f = tid + (it << 8);
        int r = f >> 2, s = f & 3;
        int x0 = s ^ (r & 3);
        float4 o = make_float4(tile[r * 16 + x0],
                               tile[r * 16 + 4 + x0],
                               tile[r * 16 + 8 + x0],
                               tile[r * 16 + 12 + x0]);
        *(float4*)(dt + (size_t)f * 4) = o;
    }
}

// All four weight packs in ONE launch (bn rows: 0-15 wq, 16-19 wk, 20-23 wv,
// 24-39 wo; all have K=2048 so bk extent matches).
__global__ void pack_w_all(
    const float* __restrict__ wq, const float* __restrict__ wk,
    const float* __restrict__ wv, const float* __restrict__ wo,
    float* __restrict__ wqp, float* __restrict__ wkp,
    float* __restrict__ wvp, float* __restrict__ wop)
{
    __shared__ __align__(16) float tile[128 * 16];
    const int bk = blockIdx.x, bny = blockIdx.y, tid = threadIdx.x;

    const float* w; float* dst; int N, bn;
    if (bny < 16)      { w = wq; dst = wqp; N = 2048; bn = bny; }
    else if (bny < 20) { w = wk; dst = wkp; N = 512;  bn = bny - 16; }
    else if (bny < 24) { w = wv; dst = wvp; N = 512;  bn = bny - 20; }
    else               { w = wo; dst = wop; N = 2048; bn = bny - 24; }
    const int K = 2048;

#pragma unroll
    for (int it = 0; it < 8; it++) {
        int idx = tid + (it << 8);
        int c = idx >> 7, r = idx & 127;
        tile[r * 16 + c] =
            to_tf32(w[(size_t)(bk * 16 + c) * N + bn * 128 + r]);
    }
    __syncthreads();

    float* dt = dst + ((size_t)bn * (K >> 4) + bk) * 2048;
#pragma unroll
    for (int it = 0; it < 2; it++) {
        int f = tid + (it << 8);
        int r = f >> 2, s = f & 3;
        int x0 = s ^ (r & 3);
        float4 o = make_float4(tile[r * 16 + x0],
                               tile[r * 16 + 4 + x0],
                               tile[r * 16 + 8 + x0],
                               tile[r * 16 + 12 + x0]);
        *(float4*)(dt + (size_t)f * 4) = o;
    }
}

// ===========================================================================
// cp.async TF32 GEMM (unchanged — validated)
// ===========================================================================
__global__ __launch_bounds__(256) void gemm_cp(
    const float* __restrict__ Ap,
    const float* __restrict__ w0, const float* __restrict__ w1,
    const float* __restrict__ w2,
    float* __restrict__ c0p, float* __restrict__ c1p, float* __restrict__ c2p,
    int K, int mode)
{
    __shared__ __align__(16) float sm[3 * 2048 * 2];   // 49152 B
    float* AsF = sm;
    float* BsF = sm + 6144;

    const int tid  = threadIdx.x;
    const int lane = tid & 31;
    const int wid  = tid >> 5;
    const int g    = lane >> 2;
    const int t    = lane & 3;
    const int wrow = wid & 3;
    const int wcol = wid >> 2;
    const int sw4  = t ^ (g & 3);

    const float* Wp; float* C; int Ncols, bn;
    const int bx = blockIdx.x;
    if (mode == 0) {
        if (bx < 16)      { Wp = w0; C = c0p; Ncols = 2048; bn = bx; }
        else if (bx < 20) { Wp = w1; C = c1p; Ncols = 512;  bn = bx - 16; }
        else              { Wp = w2; C = c2p; Ncols = 512;  bn = bx - 20; }
    } else { Wp = w0; C = c0p; Ncols = 2048; bn = bx; }
    const int bm  = blockIdx.y;
    const int nkt = K >> 4;

    const float* Abase = Ap + (size_t)bm * nkt * 2048;
    const float* Bbase = Wp + (size_t)bn * nkt * 2048;
    const uint32_t sA = smem_u32(AsF), sB = smem_u32(BsF);

    float4 c[2][8];
#pragma unroll
    for (int i = 0; i < 2; i++)
#pragma unroll
        for (int j = 0; j < 8; j++) c[i][j] = make_float4(0.f, 0.f, 0.f, 0.f);

#pragma unroll
    for (int s = 0; s < 2; s++) {
        const float* at = Abase + (size_t)s * 2048;
        const float* bt = Bbase + (size_t)s * 2048;
#pragma unroll
        for (int it = 0; it < 2; it++) {
            int f = tid + (it << 8);
            cp16(sA + (uint32_t)(s * 2048 + f * 4) * 4, at + (size_t)f * 4);
            cp16(sB + (uint32_t)(s * 2048 + f * 4) * 4, bt + (size_t)f * 4);
        }
        CP_COMMIT();
    }

    for (int kb = 0; kb < nkt; kb++) {
        CP_WAIT1();
        __syncthreads();

        const int ns = kb + 2;
        if (ns < nkt) {
            const int slot = ns % 3;
            const float* at = Abase + (size_t)ns * 2048;
            const float* bt = Bbase + (size_t)ns * 2048;
#pragma unroll
            for (int it = 0; it < 2; it++) {
                int f = tid + (it << 8);
                cp16(sA + (uint32_t)(slot * 2048 + f * 4) * 4, at + (size_t)f * 4);
                cp16(sB + (uint32_t)(slot * 2048 + f * 4) * 4, bt + (size_t)f * 4);
            }
        }
        CP_COMMIT();

        const float4* As4 = (const float4*)(AsF + (kb % 3) * 2048);
        const float4* Bs4 = (const float4*)(BsF + (kb % 3) * 2048);

        float4 afl[2], afh[2], bf[8];
#pragma unroll
        for (int i = 0; i < 2; i++) {
            int rl = wrow * 32 + i * 16 + g;
            afl[i] = As4[rl * 4 + sw4];
            afh[i] = As4[(rl + 8) * 4 + sw4];
        }
#pragma unroll
        for (int j = 0; j < 8; j++)
            bf[j] = Bs4[(wcol * 64 + j * 8 + g) * 4 + sw4];

#pragma unroll
        for (int i = 0; i < 2; i++) {
            uint32_t a0 = f2u(afl[i].x), a1 = f2u(afh[i].x);
            uint32_t a2 = f2u(afl[i].y), a3 = f2u(afh[i].y);
#pragma unroll
            for (int j = 0; j < 8; j++)
                mma_tf32(c[i][j], a0, a1, a2, a3, f2u(bf[j].x), f2u(bf[j].y));
        }
#pragma unroll
        for (int i = 0; i < 2; i++) {
            uint32_t a0 = f2u(afl[i].z), a1 = f2u(afh[i].z);
            uint32_t a2 = f2u(afl[i].w), a3 = f2u(afh[i].w);
#pragma unroll
            for (int j = 0; j < 8; j++)
                mma_tf32(c[i][j], a0, a1, a2, a3, f2u(bf[j].z), f2u(bf[j].w));
        }
    }
    CP_WAIT0();

    const int row0 = bm * 128, col0 = bn * 128;
#pragma unroll
    for (int i = 0; i < 2; i++) {
        int r = row0 + wrow * 32 + i * 16 + g;
#pragma unroll
        for (int j = 0; j < 8; j++) {
            int cc = col0 + wcol * 64 + j * 8 + 2 * t;
            *(float2*)(C + (size_t)r * Ncols + cc)       = make_float2(c[i][j].x, c[i][j].y);
            *(float2*)(C + (size_t)(r + 8) * Ncols + cc) = make_float2(c[i][j].z, c[i][j].w);
        }
    }
}

// ---------------------------------------------------------------------------
// RoPE
// ---------------------------------------------------------------------------
__global__ void rope_kernel(float* __restrict__ q, float* __restrict__ k)
{
    const int PPT = (NH + NKV) * (HD / 2);   // 1280
    int idx = blockIdx.x * blockDim.x + threadIdx.x;
    if (idx >= M_TOK * PPT) return;

    int m    = idx / PPT;
    int r    = idx - m * PPT;
    int head = r >> 6;
    int i    = r & 63;
    int t    = m & (T_ - 1);

    float ang = (float)t * g_invf[i];
    float s, c;
    sincosf(ang, &s, &c);

    float* base = (head < NH)
        ? (q + (size_t)m * QCOLS + head * HD)
        : (k + (size_t)m * KVCOLS + (head - NH) * HD);

    float u1 = base[i];
    float u2 = base[i + 64];
    base[i]      = u1 * c - u2 * s;
    base[i + 64] = u2 * c + u1 * s;
}

// ===========================================================================
// pack_kv: build flash-ready K/V tiles in gmem. One block per (kt, kvh, b).
// Stages the EXACT smem images the flash fragment loaders expect (pad-free:
// K chunk stride 1024, V chunk stride 2048), then streams them out as
// contiguous float4. Same cvt.rna values as the R9 in-flash converters.
// ===========================================================================
__global__ __launch_bounds__(256) void pack_kv(
    const float* __restrict__ k, const float* __restrict__ v,
    float* __restrict__ kp, float* __restrict__ vp)
{
    __shared__ __align__(16) float stage[16384];   // K [0,8192), V [8192,16384)
    const int kt  = blockIdx.x;      // 0..31
    const int kvh = blockIdx.y;      // 0..3
    const int b   = blockIdx.z;      // 0..1
    const int tid = threadIdx.x;
    const int s0  = kt * 64;

    const float* Kbase = k + (size_t)b * T_ * KVCOLS + kvh * HD;
    const float* Vbase = v + (size_t)b * T_ * KVCOLS + kvh * HD;

    for (int l = tid; l < 2048; l += 256) {
        int s  = l >> 5;
        int d4 = (l & 31) << 2;
        float4 vv = *(const float4*)(Kbase + (size_t)(s0 + s) * KVCOLS + d4);
        int base = (d4 >> 4) * 1024 + s * 16 + ((d4 >> 2) & 3);
        int s3 = s & 3;
        stage[base + ((0 ^ s3) << 2)] = to_tf32(vv.x);
        stage[base + ((1 ^ s3) << 2)] = to_tf32(vv.y);
        stage[base + ((2 ^ s3) << 2)] = to_tf32(vv.z);
        stage[base + ((3 ^ s3) << 2)] = to_tf32(vv.w);
    }
    for (int l = tid; l < 2048; l += 256) {
        int s  = l & 63;
        int d4 = (l >> 6) << 2;
        float4 vv = *(const float4*)(Vbase + (size_t)(s0 + s) * KVCOLS + d4);
        int s3 = s & 3;
        int cb = 8192 + (s >> 4) * 2048 + ((s >> 2) & 3);
        stage[cb + (d4 + 0) * 16 + ((s3 ^ 0) << 2)] = to_tf32(vv.x);
        stage[cb + (d4 + 1) * 16 + ((s3 ^ 1) << 2)] = to_tf32(vv.y);
        stage[cb + (d4 + 2) * 16 + ((s3 ^ 2) << 2)] = to_tf32(vv.z);
        stage[cb + (d4 + 3) * 16 + ((s3 ^ 3) << 2)] = to_tf32(vv.w);
    }
    __syncthreads();

    const size_t tbase = (size_t)((b * NKV + kvh) * 32 + kt) * 8192;
    float4* kd = (float4*)(kp + tbase);
    float4* vd = (float4*)(vp + tbase);
    const float4* st4 = (const float4*)stage;
    for (int i = tid; i < 2048; i += 256) kd[i] = st4[i];
    for (int i = tid; i < 2048; i += 256) vd[i] = st4[2048 + i];
}

// ===========================================================================
// TF32 flash attention, BM=128 — now with cp.async K double-buffer + V
// single-buffer prefetch on pre-packed tiles. Fragment math bit-identical
// to the R9 passing kernel.
// smem: Q 8x2052, K 2x(8x1028), V 4x2064, P 4x2052 = 49328 fl = 197312 B.
// ===========================================================================
#define QS_F   (8 * 2052)
#define KS_B   (8 * 1028)          // one K buffer
#define VS_F   (4 * 2064)
#define PS_F   (4 * 2052)
#define FLASH_SMEM ((QS_F + 2 * KS_B + VS_F + PS_F) * (int)sizeof(float))

__global__ __launch_bounds__(256, 1) void flash_tf32(
    const float* __restrict__ Qg, const float* __restrict__ Kp,
    const float* __restrict__ Vp, float* __restrict__ Og)
{
    extern __shared__ float smf[];
    float* Qs = smf;
    float* Ks = Qs + QS_F;          // 2 buffers
    float* Vs = Ks + 2 * KS_B;
    float* Ps = Vs + VS_F;
    const float4* Qs4 = (const float4*)Qs;
    const float4* Vs4 = (const float4*)Vs;
    const float4* Ps4 = (const float4*)Ps;
    const uint32_t sKs = smem_u32(Ks), sVs = smem_u32(Vs);

    const int tid  = threadIdx.x;
    const int lane = tid & 31;
    const int wid  = tid >> 5;
    const int g    = lane >> 2;
    const int t    = lane & 3;
    const int sw   = t ^ (g & 3);
    const int qb   = (int)gridDim.x - 1 - (int)blockIdx.x;  // heavy first
    const int h    = blockIdx.y;
    const int b    = blockIdx.z;
    const int kvh  = h >> 2;
    const int q0   = qb * 128;
    const int rl   = wid * 16 + g;
    const float scale = 0.08838834764831845f;

    const float* Qbase = Qg + (size_t)b * T_ * QCOLS + h * HD;
    const float* Ktile = Kp + (size_t)((b * NKV + kvh) * 32) * 8192;
    const float* Vtile = Vp + (size_t)((b * NKV + kvh) * 32) * 8192;

    // ---- prologue: prefetch K[0] ----
    {
        const float* src = Ktile;
#pragma unroll
        for (int it = 0; it < 8; it++) {
            int idx = tid + (it << 8);
            int ch = idx >> 8, win = idx & 255;
            cp16(sKs + (uint32_t)(ch * 1028 + win * 4) * 4, src + (size_t)idx * 4);
        }
        CP_COMMIT();
    }

    // ---- load Q tile [128 rows][128 dims] (unchanged) ----
    for (int l = tid; l < 4096; l += 256) {
        int r  = l >> 5;
        int d4 = (l & 31) << 2;
        float4 v = *(const float4*)(Qbase + (size_t)(q0 + r) * QCOLS + d4);
        int base = (d4 >> 4) * 2052 + r * 16 + ((d4 >> 2) & 3);
        int r3 = r & 3;
        Qs[base + ((0 ^ r3) << 2)] = to_tf32(v.x);
        Qs[base + ((1 ^ r3) << 2)] = to_tf32(v.y);
        Qs[base + ((2 ^ r3) << 2)] = to_tf32(v.z);
        Qs[base + ((3 ^ r3) << 2)] = to_tf32(v.w);
    }

    float4 o[16];
#pragma unroll
    for (int j = 0; j < 16; j++) o[j] = make_float4(0.f, 0.f, 0.f, 0.f);
    float m0 = -1e30f, m1 = -1e30f, l0 = 0.f, l1 = 0.f;

    const int ktmax = 2 * qb + 1;
    for (int kt = 0; kt <= ktmax; kt++) {
        // issue V[kt] (own group), then K[kt+1] (own group)
        {
            const float* src = Vtile + (size_t)kt * 8192;
#pragma unroll
            for (int it = 0; it < 8; it++) {
                int idx = tid + (it << 8);
                int ch = idx >> 9, win = idx & 511;
                cp16(sVs + (uint32_t)(ch * 2064 + win * 4) * 4, src + (size_t)idx * 4);
            }
            CP_COMMIT();
        }
        if (kt < ktmax) {
            const float* src = Ktile + (size_t)(kt + 1) * 8192;
            const uint32_t kb = sKs + (uint32_t)(((kt + 1) & 1) * KS_B) * 4;
#pragma unroll
            for (int it = 0; it < 8; it++) {
                int idx = tid + (it << 8);
                int ch = idx >> 8, win = idx & 255;
                cp16(kb + (uint32_t)(ch * 1028 + win * 4) * 4, src + (size_t)idx * 4);
            }
        }
        CP_COMMIT();

        CP_WAIT2();            // K[kt] landed (V[kt], K[kt+1] may be in flight)
        __syncthreads();

        const float4* Ks4 = (const float4*)(Ks + (kt & 1) * KS_B);

        // ---- S = Q @ K^T (warp: m16 x n64 x k128) ----
        float4 c[8];
#pragma unroll
        for (int j = 0; j < 8; j++) c[j] = make_float4(0.f, 0.f, 0.f, 0.f);

#pragma unroll
        for (int kc = 0; kc < 8; kc++) {
            float4 aL = Qs4[kc * 513 + rl * 4 + sw];
            float4 aH = Qs4[kc * 513 + (rl + 8) * 4 + sw];
            uint32_t x0 = f2u(aL.x), x1 = f2u(aH.x), x2 = f2u(aL.y), x3 = f2u(aH.y);
            uint32_t z0 = f2u(aL.z), z1 = f2u(aH.z), z2 = f2u(aL.w), z3 = f2u(aH.w);
#pragma unroll
            for (int j = 0; j < 8; j++) {
                float4 bv = Ks4[kc * 257 + (8 * j + g) * 4 + sw];
                mma_tf32(c[j], x0, x1, x2, x3, f2u(bv.x), f2u(bv.y));
                mma_tf32(c[j], z0, z1, z2, z3, f2u(bv.z), f2u(bv.w));
            }
        }

#pragma unroll
        for (int j = 0; j < 8; j++) {
            c[j].x *= scale; c[j].y *= scale; c[j].z *= scale; c[j].w *= scale;
        }

        const int s0 = kt * 64;
        if (kt >= 2 * qb) {     // diagonal-crossing tiles
            const int row_lo = q0 + rl, row_hi = row_lo + 8;
#pragma unroll
            for (int j = 0; j < 8; j++) {
                int col = s0 + 8 * j + 2 * t;
                if (col     > row_lo) c[j].x = -1e30f;
                if (col + 1 > row_lo) c[j].y = -1e30f;
                if (col     > row_hi) c[j].z = -1e30f;
                if (col + 1 > row_hi) c[j].w = -1e30f;
            }
        }

        // ---- online softmax ----
        float mt0 = -1e30f, mt1 = -1e30f;
#pragma unroll
        for (int j = 0; j < 8; j++) {
            mt0 = fmaxf(mt0, fmaxf(c[j].x, c[j].y));
            mt1 = fmaxf(mt1, fmaxf(c[j].z, c[j].w));
        }
#pragma unroll
        for (int off = 1; off <= 2; off <<= 1) {
            mt0 = fmaxf(mt0, __shfl_xor_sync(0xffffffffu, mt0, off));
            mt1 = fmaxf(mt1, __shfl_xor_sync(0xffffffffu, mt1, off));
        }
        float m0n = fmaxf(m0, mt0), m1n = fmaxf(m1, mt1);
        float corr0 = __expf(m0 - m0n), corr1 = __expf(m1 - m1n);

        float rs0 = 0.f, rs1 = 0.f;
#pragma unroll
        for (int j = 0; j < 8; j++) {
            c[j].x = __expf(c[j].x - m0n);
            c[j].y = __expf(c[j].y - m0n);
            c[j].z = __expf(c[j].z - m1n);
            c[j].w = __expf(c[j].w - m1n);
            rs0 += c[j].x + c[j].y;
            rs1 += c[j].z + c[j].w;
        }
#pragma unroll
        for (int off = 1; off <= 2; off <<= 1) {
            rs0 += __shfl_xor_sync(0xffffffffu, rs0, off);
            rs1 += __shfl_xor_sync(0xffffffffu, rs1, off);
        }
        l0 = l0 * corr0 + rs0;  m0 = m0n;
        l1 = l1 * corr1 + rs1;  m1 = m1n;

#pragma unroll
        for (int j = 0; j < 16; j++) {
            o[j].x *= corr0; o[j].y *= corr0;
            o[j].z *= corr1; o[j].w *= corr1;
        }

        CP_WAIT1();            // V[kt] landed (K[kt+1] may still be in flight)
        __syncthreads();

        // ---- store P (warp-private rows) ----
        {
            const int r3 = rl & 3;
#pragma unroll
            for (int j = 0; j < 8; j++) {
                int cx = 8 * j + 2 * t;
                int cy = cx + 1;
                int bx = (cx >> 4) * 2052 + (((cx & 3) ^ r3) << 2) + ((cx >> 2) & 3);
                int by = (cy >> 4) * 2052 + (((cy & 3) ^ r3) << 2) + ((cy >> 2) & 3);
                Ps[bx + rl * 16]       = to_tf32(c[j].x);
                Ps[by + rl * 16]       = to_tf32(c[j].y);
                Ps[bx + (rl + 8) * 16] = to_tf32(c[j].z);
                Ps[by + (rl + 8) * 16] = to_tf32(c[j].w);
            }
        }
        __syncwarp();

        // ---- O += P @ V (warp: m16 x n128 x k64) ----
#pragma unroll
        for (int kc = 0; kc < 4; kc++) {
            float4 aL = Ps4[kc * 513 + rl * 4 + sw];
            float4 aH = Ps4[kc * 513 + (rl + 8) * 4 + sw];
            uint32_t x0 = f2u(aL.x), x1 = f2u(aH.x), x2 = f2u(aL.y), x3 = f2u(aH.y);
            uint32_t z0 = f2u(aL.z), z1 = f2u(aH.z), z2 = f2u(aL.w), z3 = f2u(aH.w);
#pragma unroll
            for (int j = 0; j < 16; j++) {
                float4 bv = Vs4[kc * 516 + (8 * j + g) * 4 + sw];
                mma_tf32(o[j], x0, x1, x2, x3, f2u(bv.x), f2u(bv.y));
                mma_tf32(o[j], z0, z1, z2, z3, f2u(bv.z), f2u(bv.w));
            }
        }
        __syncthreads();       // protect Vs / K-alt-buffer before next issues
    }
    CP_WAIT0();

    // ---- epilogue ----
    float i0 = 1.0f / l0, i1 = 1.0f / l1;
    float* Obase = Og + (size_t)b * T_ * QCOLS + h * HD;
    const int rA = q0 + rl, rB = rA + 8;
#pragma unroll
    for (int j = 0; j < 16; j++) {
        int col = 8 * j + 2 * t;
        *(float2*)(Obase + (size_t)rA * QCOLS + col) = make_float2(o[j].x * i0, o[j].y * i0);
        *(float2*)(Obase + (size_t)rB * QCOLS + col) = make_float2(o[j].z * i1, o[j].w * i1);
    }
}

// ---------------------------------------------------------------------------
// Launch  (flash is the 6th launch -> captured by ncu -s 5 -c 1)
// ---------------------------------------------------------------------------
extern "C" void kernel_launch(void* const* d_in, const int* in_sizes, int n_in,
                              void* d_out, int out_size)
{
    const float* x  = (const float*)d_in[0];
    const float* wq = (const float*)d_in[1];
    const float* wk = (const float*)d_in[2];
    const float* wv = (const float*)d_in[3];
    const float* wo = (const float*)d_in[4];
    float* out = (float*)d_out;

    float *q, *k, *v, *att, *xp, *attp, *wqp, *wkp, *wvp, *wop, *kp, *vp;
    cudaGetSymbolAddress((void**)&q,    g_q);
    cudaGetSymbolAddress((void**)&k,    g_k);
    cudaGetSymbolAddress((void**)&v,    g_v);
    cudaGetSymbolAddress((void**)&att,  g_att);
    cudaGetSymbolAddress((void**)&xp,   g_xp);
    cudaGetSymbolAddress((void**)&attp, g_attp);
    cudaGetSymbolAddress((void**)&wqp,  g_wqp);
    cudaGetSymbolAddress((void**)&wkp,  g_wkp);
    cudaGetSymbolAddress((void**)&wvp,  g_wvp);
    cudaGetSymbolAddress((void**)&wop,  g_wop);
    cudaGetSymbolAddress((void**)&kp,   g_kp);
    cudaGetSymbolAddress((void**)&vp,   g_vp);

    cudaFuncSetAttribute(flash_tf32,
                         cudaFuncAttributeMaxDynamicSharedMemorySize, FLASH_SMEM);

    // [0] pack x (also seeds invf table)
    pack_act<<<dim3(D_ / 16, M_TOK / 128), 256>>>(x, xp, D_);
    // [1] pack all weights
    pack_w_all<<<dim3(128, 40), 256>>>(wq, wk, wv, wo, wqp, wkp, wvp, wop);
    // [2] fused QKV projection
    gemm_cp<<<dim3(24, 32), 256>>>(xp, wqp, wkp, wvp, q, k, v, D_, 0);
    // [3] RoPE
    int total_pairs = M_TOK * (NH + NKV) * (HD / 2);
    rope_kernel<<<(total_pairs + 255) / 256, 256>>>(q, k);
    // [4] pack K/V into flash-ready tiles
    pack_kv<<<dim3(32, NKV, B_), 256>>>(k, v, kp, vp);
    // [5] causal GQA flash attention  <-- ncu capture target
    flash_tf32<<<dim3(T_ / 128, NH, B_), 256, FLASH_SMEM>>>(q, kp, vp, att);
    // [6] pack attention output
    pack_act<<<dim3(QCOLS / 16, M_TOK / 128), 256>>>(att, attp, QCOLS);
    // [7] output projection
    gemm_cp<<<dim3(16, 32), 256>>>(attp, wop, nullptr, nullptr,
                                   out, nullptr, nullptr, QCOLS, 1);
}

// round 14
// speedup vs baseline: 7.8997x; 1.0576x over previous
#include <cuda_runtime.h>
#include <math.h>
#include <stdint.h>

// ---------------------------------------------------------------------------
// Problem constants
// ---------------------------------------------------------------------------
#define B_      2
#define T_      2048
#define D_      2048
#define NH      16
#define NKV     4
#define HD      128
#define M_TOK   (B_ * T_)          // 4096
#define QCOLS   (NH * HD)          // 2048
#define KVCOLS  (NKV * HD)         // 512

// ---------------------------------------------------------------------------
// Scratch
// ---------------------------------------------------------------------------
__device__ float g_q  [M_TOK * QCOLS];
__device__ float g_k  [M_TOK * KVCOLS];
__device__ float g_v  [M_TOK * KVCOLS];
__device__ float g_att[M_TOK * QCOLS];
__device__ float g_invf[64];
// MMA-ready packed operands (tf32-rounded, tile-permuted)
__device__ float g_xp  [M_TOK * D_];
__device__ float g_attp[M_TOK * QCOLS];
__device__ float g_wqp [D_ * QCOLS];
__device__ float g_wkp [D_ * KVCOLS];
__device__ float g_wvp [D_ * KVCOLS];
__device__ float g_wop [QCOLS * D_];
// flash-ready packed K/V tiles (pre-swizzled smem images, 8192 floats/tile)
__device__ float g_kp  [M_TOK * KVCOLS];
__device__ float g_vp  [M_TOK * KVCOLS];

// ---------------------------------------------------------------------------
// helpers
// ---------------------------------------------------------------------------
__device__ __forceinline__ float to_tf32(float x) {
    uint32_t u;
    asm("cvt.rna.tf32.f32 %0, %1;" : "=r"(u) : "f"(x));
    return __uint_as_float(u);
}
__device__ __forceinline__ uint32_t f2u(float x) { return __float_as_uint(x); }

__device__ __forceinline__ uint32_t smem_u32(const void* p) {
    uint32_t a;
    asm("{ .reg .u64 t; cvta.to.shared.u64 t, %1; cvt.u32.u64 %0, t; }"
        : "=r"(a) : "l"(p));
    return a;
}
__device__ __forceinline__ void cp16(uint32_t dst, const void* src) {
    asm volatile("cp.async.cg.shared.global [%0], [%1], 16;"
                 :: "r"(dst), "l"(src) : "memory");
}
#define CP_COMMIT() asm volatile("cp.async.commit_group;" ::: "memory")
#define CP_WAIT1()  asm volatile("cp.async.wait_group 1;" ::: "memory")
#define CP_WAIT0()  asm volatile("cp.async.wait_group 0;" ::: "memory")

__device__ __forceinline__ void mma_tf32(float4& d,
    uint32_t a0, uint32_t a1, uint32_t a2, uint32_t a3,
    uint32_t b0, uint32_t b1)
{
    asm volatile(
        "mma.sync.aligned.m16n8k8.row.col.f32.tf32.tf32.f32 "
        "{%0,%1,%2,%3}, {%4,%5,%6,%7}, {%8,%9}, {%0,%1,%2,%3};"
        : "+f"(d.x), "+f"(d.y), "+f"(d.z), "+f"(d.w)
        : "r"(a0), "r"(a1), "r"(a2), "r"(a3), "r"(b0), "r"(b1));
}

// ===========================================================================
// Pack kernels (GEMM operands) — validated. pack_act also seeds invf table.
// ===========================================================================
__global__ void pack_act(const float* __restrict__ src, float* __restrict__ dst,
                         int K)
{
    __shared__ __align__(16) float tile[128 * 16];
    const int bk = blockIdx.x, bm = blockIdx.y, tid = threadIdx.x;

    if (bk == 0 && bm == 0 && tid < 64)
        g_invf[tid] = (float)(1.0 / pow(1.0e6, (double)tid / 64.0));

#pragma unroll
    for (int it = 0; it < 2; it++) {
        int idx = tid + (it << 8);
        int r = idx >> 2, aqi = idx & 3;
        float4 v = *(const float4*)(src + (size_t)(bm * 128 + r) * K
                                        + bk * 16 + (aqi << 2));
        tile[r * 16 + (aqi << 2) + 0] = to_tf32(v.x);
        tile[r * 16 + (aqi << 2) + 1] = to_tf32(v.y);
        tile[r * 16 + (aqi << 2) + 2] = to_tf32(v.z);
        tile[r * 16 + (aqi << 2) + 3] = to_tf32(v.w);
    }
    __syncthreads();

    float* dt = dst + ((size_t)bm * (K >> 4) + bk) * 2048;
#pragma unroll
    for (int it = 0; it < 2; it++) {
        int f = tid + (it << 8);
        int r = f >> 2, s = f & 3;
        int x0 = s ^ (r & 3);
        float4 o = make_float4(tile[r * 16 + x0],
                               tile[r * 16 + 4 + x0],
                               tile[r * 16 + 8 + x0],
                               tile[r * 16 + 12 + x0]);
        *(float4*)(dt + (size_t)f * 4) = o;
    }
}

__global__ void pack_w_all(
    const float* __restrict__ wq, const float* __restrict__ wk,
    const float* __restrict__ wv, const float* __restrict__ wo,
    float* __restrict__ wqp, float* __restrict__ wkp,
    float* __restrict__ wvp, float* __restrict__ wop)
{
    __shared__ __align__(16) float tile[128 * 16];
    const int bk = blockIdx.x, bny = blockIdx.y, tid = threadIdx.x;

    const float* w; float* dst; int N, bn;
    if (bny < 16)      { w = wq; dst = wqp; N = 2048; bn = bny; }
    else if (bny < 20) { w = wk; dst = wkp; N = 512;  bn = bny - 16; }
    else if (bny < 24) { w = wv; dst = wvp; N = 512;  bn = bny - 20; }
    else               { w = wo; dst = wop; N = 2048; bn = bny - 24; }
    const int K = 2048;

#pragma unroll
    for (int it = 0; it < 8; it++) {
        int idx = tid + (it << 8);
        int c = idx >> 7, r = idx & 127;
        tile[r * 16 + c] =
            to_tf32(w[(size_t)(bk * 16 + c) * N + bn * 128 + r]);
    }
    __syncthreads();

    float* dt = dst + ((size_t)bn * (K >> 4) + bk) * 2048;
#pragma unroll
    for (int it = 0; it < 2; it++) {
        int f = tid + (it << 8);
        int r = f >> 2, s = f & 3;
        int x0 = s ^ (r & 3);
        float4 o = make_float4(tile[r * 16 + x0],
                               tile[r * 16 + 4 + x0],
                               tile[r * 16 + 8 + x0],
                               tile[r * 16 + 12 + x0]);
        *(float4*)(dt + (size_t)f * 4) = o;
    }
}

// ===========================================================================
// cp.async TF32 GEMM (unchanged — validated)
// ===========================================================================
__global__ __launch_bounds__(256) void gemm_cp(
    const float* __restrict__ Ap,
    const float* __restrict__ w0, const float* __restrict__ w1,
    const float* __restrict__ w2,
    float* __restrict__ c0p, float* __restrict__ c1p, float* __restrict__ c2p,
    int K, int mode)
{
    __shared__ __align__(16) float sm[3 * 2048 * 2];   // 49152 B
    float* AsF = sm;
    float* BsF = sm + 6144;

    const int tid  = threadIdx.x;
    const int lane = tid & 31;
    const int wid  = tid >> 5;
    const int g    = lane >> 2;
    const int t    = lane & 3;
    const int wrow = wid & 3;
    const int wcol = wid >> 2;
    const int sw4  = t ^ (g & 3);

    const float* Wp; float* C; int Ncols, bn;
    const int bx = blockIdx.x;
    if (mode == 0) {
        if (bx < 16)      { Wp = w0; C = c0p; Ncols = 2048; bn = bx; }
        else if (bx < 20) { Wp = w1; C = c1p; Ncols = 512;  bn = bx - 16; }
        else              { Wp = w2; C = c2p; Ncols = 512;  bn = bx - 20; }
    } else { Wp = w0; C = c0p; Ncols = 2048; bn = bx; }
    const int bm  = blockIdx.y;
    const int nkt = K >> 4;

    const float* Abase = Ap + (size_t)bm * nkt * 2048;
    const float* Bbase = Wp + (size_t)bn * nkt * 2048;
    const uint32_t sA = smem_u32(AsF), sB = smem_u32(BsF);

    float4 c[2][8];
#pragma unroll
    for (int i = 0; i < 2; i++)
#pragma unroll
        for (int j = 0; j < 8; j++) c[i][j] = make_float4(0.f, 0.f, 0.f, 0.f);

#pragma unroll
    for (int s = 0; s < 2; s++) {
        const float* at = Abase + (size_t)s * 2048;
        const float* bt = Bbase + (size_t)s * 2048;
#pragma unroll
        for (int it = 0; it < 2; it++) {
            int f = tid + (it << 8);
            cp16(sA + (uint32_t)(s * 2048 + f * 4) * 4, at + (size_t)f * 4);
            cp16(sB + (uint32_t)(s * 2048 + f * 4) * 4, bt + (size_t)f * 4);
        }
        CP_COMMIT();
    }

    for (int kb = 0; kb < nkt; kb++) {
        CP_WAIT1();
        __syncthreads();

        const int ns = kb + 2;
        if (ns < nkt) {
            const int slot = ns % 3;
            const float* at = Abase + (size_t)ns * 2048;
            const float* bt = Bbase + (size_t)ns * 2048;
#pragma unroll
            for (int it = 0; it < 2; it++) {
                int f = tid + (it << 8);
                cp16(sA + (uint32_t)(slot * 2048 + f * 4) * 4, at + (size_t)f * 4);
                cp16(sB + (uint32_t)(slot * 2048 + f * 4) * 4, bt + (size_t)f * 4);
            }
        }
        CP_COMMIT();

        const float4* As4 = (const float4*)(AsF + (kb % 3) * 2048);
        const float4* Bs4 = (const float4*)(BsF + (kb % 3) * 2048);

        float4 afl[2], afh[2], bf[8];
#pragma unroll
        for (int i = 0; i < 2; i++) {
            int rl = wrow * 32 + i * 16 + g;
            afl[i] = As4[rl * 4 + sw4];
            afh[i] = As4[(rl + 8) * 4 + sw4];
        }
#pragma unroll
        for (int j = 0; j < 8; j++)
            bf[j] = Bs4[(wcol * 64 + j * 8 + g) * 4 + sw4];

#pragma unroll
        for (int i = 0; i < 2; i++) {
            uint32_t a0 = f2u(afl[i].x), a1 = f2u(afh[i].x);
            uint32_t a2 = f2u(afl[i].y), a3 = f2u(afh[i].y);
#pragma unroll
            for (int j = 0; j < 8; j++)
                mma_tf32(c[i][j], a0, a1, a2, a3, f2u(bf[j].x), f2u(bf[j].y));
        }
#pragma unroll
        for (int i = 0; i < 2; i++) {
            uint32_t a0 = f2u(afl[i].z), a1 = f2u(afh[i].z);
            uint32_t a2 = f2u(afl[i].w), a3 = f2u(afh[i].w);
#pragma unroll
            for (int j = 0; j < 8; j++)
                mma_tf32(c[i][j], a0, a1, a2, a3, f2u(bf[j].z), f2u(bf[j].w));
        }
    }
    CP_WAIT0();

    const int row0 = bm * 128, col0 = bn * 128;
#pragma unroll
    for (int i = 0; i < 2; i++) {
        int r = row0 + wrow * 32 + i * 16 + g;
#pragma unroll
        for (int j = 0; j < 8; j++) {
            int cc = col0 + wcol * 64 + j * 8 + 2 * t;
            *(float2*)(C + (size_t)r * Ncols + cc)       = make_float2(c[i][j].x, c[i][j].y);
            *(float2*)(C + (size_t)(r + 8) * Ncols + cc) = make_float2(c[i][j].z, c[i][j].w);
        }
    }
}

// ---------------------------------------------------------------------------
// RoPE
// ---------------------------------------------------------------------------
__global__ void rope_kernel(float* __restrict__ q, float* __restrict__ k)
{
    const int PPT = (NH + NKV) * (HD / 2);   // 1280
    int idx = blockIdx.x * blockDim.x + threadIdx.x;
    if (idx >= M_TOK * PPT) return;

    int m    = idx / PPT;
    int r    = idx - m * PPT;
    int head = r >> 6;
    int i    = r & 63;
    int t    = m & (T_ - 1);

    float ang = (float)t * g_invf[i];
    float s, c;
    sincosf(ang, &s, &c);

    float* base = (head < NH)
        ? (q + (size_t)m * QCOLS + head * HD)
        : (k + (size_t)m * KVCOLS + (head - NH) * HD);

    float u1 = base[i];
    float u2 = base[i + 64];
    base[i]      = u1 * c - u2 * s;
    base[i + 64] = u2 * c + u1 * s;
}

// ===========================================================================
// pack_kv (unchanged — validated)
// ===========================================================================
__global__ __launch_bounds__(256) void pack_kv(
    const float* __restrict__ k, const float* __restrict__ v,
    float* __restrict__ kp, float* __restrict__ vp)
{
    __shared__ __align__(16) float stage[16384];
    const int kt  = blockIdx.x;
    const int kvh = blockIdx.y;
    const int b   = blockIdx.z;
    const int tid = threadIdx.x;
    const int s0  = kt * 64;

    const float* Kbase = k + (size_t)b * T_ * KVCOLS + kvh * HD;
    const float* Vbase = v + (size_t)b * T_ * KVCOLS + kvh * HD;

    for (int l = tid; l < 2048; l += 256) {
        int s  = l >> 5;
        int d4 = (l & 31) << 2;
        float4 vv = *(const float4*)(Kbase + (size_t)(s0 + s) * KVCOLS + d4);
        int base = (d4 >> 4) * 1024 + s * 16 + ((d4 >> 2) & 3);
        int s3 = s & 3;
        stage[base + ((0 ^ s3) << 2)] = to_tf32(vv.x);
        stage[base + ((1 ^ s3) << 2)] = to_tf32(vv.y);
        stage[base + ((2 ^ s3) << 2)] = to_tf32(vv.z);
        stage[base + ((3 ^ s3) << 2)] = to_tf32(vv.w);
    }
    for (int l = tid; l < 2048; l += 256) {
        int s  = l & 63;
        int d4 = (l >> 6) << 2;
        float4 vv = *(const float4*)(Vbase + (size_t)(s0 + s) * KVCOLS + d4);
        int s3 = s & 3;
        int cb = 8192 + (s >> 4) * 2048 + ((s >> 2) & 3);
        stage[cb + (d4 + 0) * 16 + ((s3 ^ 0) << 2)] = to_tf32(vv.x);
        stage[cb + (d4 + 1) * 16 + ((s3 ^ 1) << 2)] = to_tf32(vv.y);
        stage[cb + (d4 + 2) * 16 + ((s3 ^ 2) << 2)] = to_tf32(vv.z);
        stage[cb + (d4 + 3) * 16 + ((s3 ^ 3) << 2)] = to_tf32(vv.w);
    }
    __syncthreads();

    const size_t tbase = (size_t)((b * NKV + kvh) * 32 + kt) * 8192;
    float4* kd = (float4*)(kp + tbase);
    float4* vd = (float4*)(vp + tbase);
    const float4* st4 = (const float4*)stage;
    for (int i = tid; i < 2048; i += 256) kd[i] = st4[i];
    for (int i = tid; i < 2048; i += 256) vd[i] = st4[2048 + i];
}

// ===========================================================================
// TF32 flash attention — BM=64, 128 threads, 2 CTAs/SM.
// P smem eliminated: PV A-fragments built from S registers via shuffles.
// K and V single-buffered cp.async, prefetch overlapped with compute phases.
// smem: Q 8x1028 + K 8x1028 + V 4x2064 = 24704 floats = 98816 B.
// ===========================================================================
#define QS_F   (8 * 1028)
#define KS_F   (8 * 1028)
#define VS_F   (4 * 2064)
#define FLASH_SMEM ((QS_F + KS_F + VS_F) * (int)sizeof(float))   // 98816

__global__ __launch_bounds__(128, 2) void flash_tf32(
    const float* __restrict__ Qg, const float* __restrict__ Kp,
    const float* __restrict__ Vp, float* __restrict__ Og)
{
    extern __shared__ float smf[];
    float* Qs = smf;
    float* Ks = Qs + QS_F;
    float* Vs = Ks + KS_F;
    const float4* Qs4 = (const float4*)Qs;
    const float4* Ks4 = (const float4*)Ks;
    const float4* Vs4 = (const float4*)Vs;
    const uint32_t sKs = smem_u32(Ks), sVs = smem_u32(Vs);

    const int tid  = threadIdx.x;
    const int lane = tid & 31;
    const int wid  = tid >> 5;          // 0..3
    const int g    = lane >> 2;
    const int t    = lane & 3;
    const int sw   = t ^ (g & 3);
    const int qb   = (int)gridDim.x - 1 - (int)blockIdx.x;   // heavy first
    const int h    = blockIdx.y;
    const int b    = blockIdx.z;
    const int kvh  = h >> 2;
    const int q0   = qb * 64;
    const int rl   = wid * 16 + g;
    const float scale = 0.08838834764831845f;
    const int s1l  = (lane & 28) | (t >> 1);   // shuffle src for col t
    const int s2l  = s1l + 2;                  // shuffle src for col t+4
    const bool odd = (t & 1) != 0;

    const float* Qbase = Qg + (size_t)b * T_ * QCOLS + h * HD;
    const float* Ktile = Kp + (size_t)((b * NKV + kvh) * 32) * 8192;
    const float* Vtile = Vp + (size_t)((b * NKV + kvh) * 32) * 8192;

    // ---- prologue: prefetch K[0] then V[0] (separate groups) ----
#pragma unroll
    for (int it = 0; it < 16; it++) {
        int idx = tid + (it << 7);
        int ch = idx >> 8, win = idx & 255;
        cp16(sKs + (uint32_t)(ch * 1028 + win * 4) * 4, Ktile + (size_t)idx * 4);
    }
    CP_COMMIT();
#pragma unroll
    for (int it = 0; it < 16; it++) {
        int idx = tid + (it << 7);
        int ch = idx >> 9, win = idx & 511;
        cp16(sVs + (uint32_t)(ch * 2064 + win * 4) * 4, Vtile + (size_t)idx * 4);
    }
    CP_COMMIT();

    // ---- load Q tile [64 rows][128 dims] ----
    for (int l = tid; l < 2048; l += 128) {
        int r  = l >> 5;
        int d4 = (l & 31) << 2;
        float4 v = *(const float4*)(Qbase + (size_t)(q0 + r) * QCOLS + d4);
        int base = (d4 >> 4) * 1028 + r * 16 + ((d4 >> 2) & 3);
        int r3 = r & 3;
        Qs[base + ((0 ^ r3) << 2)] = to_tf32(v.x);
        Qs[base + ((1 ^ r3) << 2)] = to_tf32(v.y);
        Qs[base + ((2 ^ r3) << 2)] = to_tf32(v.z);
        Qs[base + ((3 ^ r3) << 2)] = to_tf32(v.w);
    }

    CP_WAIT1();            // K[0] landed (V[0] in flight)
    __syncthreads();       // K visible + Q stores done

    float4 o[16];
#pragma unroll
    for (int j = 0; j < 16; j++) o[j] = make_float4(0.f, 0.f, 0.f, 0.f);
    float m0 = -1e30f, m1 = -1e30f, l0 = 0.f, l1 = 0.f;

    for (int kt = 0; kt <= qb; kt++) {
        // ---- S = Q @ K^T (warp: m16 x n64 x k128) ----
        float4 c[8];
#pragma unroll
        for (int j = 0; j < 8; j++) c[j] = make_float4(0.f, 0.f, 0.f, 0.f);

#pragma unroll
        for (int kc = 0; kc < 8; kc++) {
            float4 aL = Qs4[kc * 257 + rl * 4 + sw];
            float4 aH = Qs4[kc * 257 + (rl + 8) * 4 + sw];
            uint32_t x0 = f2u(aL.x), x1 = f2u(aH.x), x2 = f2u(aL.y), x3 = f2u(aH.y);
            uint32_t z0 = f2u(aL.z), z1 = f2u(aH.z), z2 = f2u(aL.w), z3 = f2u(aH.w);
#pragma unroll
            for (int j = 0; j < 8; j++) {
                float4 bv = Ks4[kc * 257 + (8 * j + g) * 4 + sw];
                mma_tf32(c[j], x0, x1, x2, x3, f2u(bv.x), f2u(bv.y));
                mma_tf32(c[j], z0, z1, z2, z3, f2u(bv.z), f2u(bv.w));
            }
        }
        __syncthreads();   // all warps done reading K buffer

        // issue K[kt+1] into the (now free) K buffer
        if (kt < qb) {
            const float* src = Ktile + (size_t)(kt + 1) * 8192;
#pragma unroll
            for (int it = 0; it < 16; it++) {
                int idx = tid + (it << 7);
                int ch = idx >> 8, win = idx & 255;
                cp16(sKs + (uint32_t)(ch * 1028 + win * 4) * 4, src + (size_t)idx * 4);
            }
        }
        CP_COMMIT();       // pending: V[kt], K[kt+1]

#pragma unroll
        for (int j = 0; j < 8; j++) {
            c[j].x *= scale; c[j].y *= scale; c[j].z *= scale; c[j].w *= scale;
        }

        const int s0 = kt * 64;
        if (kt == qb) {    // diagonal tile: mask col > row
            const int row_lo = q0 + rl, row_hi = row_lo + 8;
#pragma unroll
            for (int j = 0; j < 8; j++) {
                int col = s0 + 8 * j + 2 * t;
                if (col     > row_lo) c[j].x = -1e30f;
                if (col + 1 > row_lo) c[j].y = -1e30f;
                if (col     > row_hi) c[j].z = -1e30f;
                if (col + 1 > row_hi) c[j].w = -1e30f;
            }
        }

        // ---- online softmax ----
        float mt0 = -1e30f, mt1 = -1e30f;
#pragma unroll
        for (int j = 0; j < 8; j++) {
            mt0 = fmaxf(mt0, fmaxf(c[j].x, c[j].y));
            mt1 = fmaxf(mt1, fmaxf(c[j].z, c[j].w));
        }
#pragma unroll
        for (int off = 1; off <= 2; off <<= 1) {
            mt0 = fmaxf(mt0, __shfl_xor_sync(0xffffffffu, mt0, off));
            mt1 = fmaxf(mt1, __shfl_xor_sync(0xffffffffu, mt1, off));
        }
        float m0n = fmaxf(m0, mt0), m1n = fmaxf(m1, mt1);
        float corr0 = __expf(m0 - m0n), corr1 = __expf(m1 - m1n);

        float rs0 = 0.f, rs1 = 0.f;
#pragma unroll
        for (int j = 0; j < 8; j++) {
            c[j].x = __expf(c[j].x - m0n);
            c[j].y = __expf(c[j].y - m0n);
            c[j].z = __expf(c[j].z - m1n);
            c[j].w = __expf(c[j].w - m1n);
            rs0 += c[j].x + c[j].y;
            rs1 += c[j].z + c[j].w;
        }
#pragma unroll
        for (int off = 1; off <= 2; off <<= 1) {
            rs0 += __shfl_xor_sync(0xffffffffu, rs0, off);
            rs1 += __shfl_xor_sync(0xffffffffu, rs1, off);
        }
        l0 = l0 * corr0 + rs0;  m0 = m0n;
        l1 = l1 * corr1 + rs1;  m1 = m1n;

#pragma unroll
        for (int j = 0; j < 16; j++) {
            o[j].x *= corr0; o[j].y *= corr0;
            o[j].z *= corr1; o[j].w *= corr1;
        }

        CP_WAIT1();        // V[kt] landed (K[kt+1] may still be in flight)
        __syncthreads();

        // ---- O += P @ V : P fragments via warp shuffles (no smem P) ----
#pragma unroll
        for (int kc = 0; kc < 4; kc++) {
            uint32_t aE[4], aO[4];
#pragma unroll
            for (int half = 0; half < 2; half++) {
                float4 cc = c[2 * kc + half];
                cc.x = to_tf32(cc.x); cc.y = to_tf32(cc.y);
                cc.z = to_tf32(cc.z); cc.w = to_tf32(cc.w);
                float xa = __shfl_sync(0xffffffffu, cc.x, s1l);
                float ya = __shfl_sync(0xffffffffu, cc.y, s1l);
                float za = __shfl_sync(0xffffffffu, cc.z, s1l);
                float wa = __shfl_sync(0xffffffffu, cc.w, s1l);
                float xb = __shfl_sync(0xffffffffu, cc.x, s2l);
                float yb = __shfl_sync(0xffffffffu, cc.y, s2l);
                float zb = __shfl_sync(0xffffffffu, cc.z, s2l);
                float wb = __shfl_sync(0xffffffffu, cc.w, s2l);
                uint32_t* a = half ? aO : aE;
                a[0] = f2u(odd ? ya : xa);   // P[rl  ][8jj + t]
                a[1] = f2u(odd ? wa : za);   // P[rl+8][8jj + t]
                a[2] = f2u(odd ? yb : xb);   // P[rl  ][8jj + t+4]
                a[3] = f2u(odd ? wb : zb);   // P[rl+8][8jj + t+4]
            }
#pragma unroll
            for (int j = 0; j < 16; j++) {
                float4 bv = Vs4[kc * 516 + (8 * j + g) * 4 + sw];
                mma_tf32(o[j], aE[0], aE[1], aE[2], aE[3], f2u(bv.x), f2u(bv.y));
                mma_tf32(o[j], aO[0], aO[1], aO[2], aO[3], f2u(bv.z), f2u(bv.w));
            }
        }
        __syncthreads();   // all warps done reading V buffer

        // issue V[kt+1] into the (now free) V buffer
        if (kt < qb) {
            const float* src = Vtile + (size_t)(kt + 1) * 8192;
#pragma unroll
            for (int it = 0; it < 16; it++) {
                int idx = tid + (it << 7);
                int ch = idx >> 9, win = idx & 511;
                cp16(sVs + (uint32_t)(ch * 2064 + win * 4) * 4, src + (size_t)idx * 4);
            }
        }
        CP_COMMIT();       // pending: K[kt+1], V[kt+1]

        CP_WAIT1();        // K[kt+1] landed
        __syncthreads();
    }
    CP_WAIT0();

    // ---- epilogue ----
    float i0 = 1.0f / l0, i1 = 1.0f / l1;
    float* Obase = Og + (size_t)b * T_ * QCOLS + h * HD;
    const int rA = q0 + rl, rB = rA + 8;
#pragma unroll
    for (int j = 0; j < 16; j++) {
        int col = 8 * j + 2 * t;
        *(float2*)(Obase + (size_t)rA * QCOLS + col) = make_float2(o[j].x * i0, o[j].y * i0);
        *(float2*)(Obase + (size_t)rB * QCOLS + col) = make_float2(o[j].z * i1, o[j].w * i1);
    }
}

// ---------------------------------------------------------------------------
// Launch
// ---------------------------------------------------------------------------
extern "C" void kernel_launch(void* const* d_in, const int* in_sizes, int n_in,
                              void* d_out, int out_size)
{
    const float* x  = (const float*)d_in[0];
    const float* wq = (const float*)d_in[1];
    const float* wk = (const float*)d_in[2];
    const float* wv = (const float*)d_in[3];
    const float* wo = (const float*)d_in[4];
    float* out = (float*)d_out;

    float *q, *k, *v, *att, *xp, *attp, *wqp, *wkp, *wvp, *wop, *kp, *vp;
    cudaGetSymbolAddress((void**)&q,    g_q);
    cudaGetSymbolAddress((void**)&k,    g_k);
    cudaGetSymbolAddress((void**)&v,    g_v);
    cudaGetSymbolAddress((void**)&att,  g_att);
    cudaGetSymbolAddress((void**)&xp,   g_xp);
    cudaGetSymbolAddress((void**)&attp, g_attp);
    cudaGetSymbolAddress((void**)&wqp,  g_wqp);
    cudaGetSymbolAddress((void**)&wkp,  g_wkp);
    cudaGetSymbolAddress((void**)&wvp,  g_wvp);
    cudaGetSymbolAddress((void**)&wop,  g_wop);
    cudaGetSymbolAddress((void**)&kp,   g_kp);
    cudaGetSymbolAddress((void**)&vp,   g_vp);

    cudaFuncSetAttribute(flash_tf32,
                         cudaFuncAttributeMaxDynamicSharedMemorySize, FLASH_SMEM);

    // [0] pack x (also seeds invf table)
    pack_act<<<dim3(D_ / 16, M_TOK / 128), 256>>>(x, xp, D_);
    // [1] pack all weights
    pack_w_all<<<dim3(128, 40), 256>>>(wq, wk, wv, wo, wqp, wkp, wvp, wop);
    // [2] fused QKV projection
    gemm_cp<<<dim3(24, 32), 256>>>(xp, wqp, wkp, wvp, q, k, v, D_, 0);
    // [3] RoPE
    int total_pairs = M_TOK * (NH + NKV) * (HD / 2);
    rope_kernel<<<(total_pairs + 255) / 256, 256>>>(q, k);
    // [4] pack K/V into flash-ready tiles
    pack_kv<<<dim3(32, NKV, B_), 256>>>(k, v, kp, vp);
    // [5] causal GQA flash attention (BM=64, 2 CTAs/SM)
    flash_tf32<<<dim3(T_ / 64, NH, B_), 128, FLASH_SMEM>>>(q, kp, vp, att);
    // [6] pack attention output
    pack_act<<<dim3(QCOLS / 16, M_TOK / 128), 256>>>(att, attp, QCOLS);
    // [7] output projection
    gemm_cp<<<dim3(16, 32), 256>>>(attp, wop, nullptr, nullptr,
                                   out, nullptr, nullptr, QCOLS, 1);
}

// round 16
// speedup vs baseline: 8.0659x; 1.0210x over previous
#include <cuda_runtime.h>
#include <math.h>
#include <stdint.h>

// ---------------------------------------------------------------------------
// Problem constants
// ---------------------------------------------------------------------------
#define B_      2
#define T_      2048
#define D_      2048
#define NH      16
#define NKV     4
#define HD      128
#define M_TOK   (B_ * T_)          // 4096
#define QCOLS   (NH * HD)          // 2048
#define KVCOLS  (NKV * HD)         // 512

// ---------------------------------------------------------------------------
// Scratch
// ---------------------------------------------------------------------------
__device__ float g_q  [M_TOK * QCOLS];
__device__ float g_k  [M_TOK * KVCOLS];
__device__ float g_v  [M_TOK * KVCOLS];
__device__ float g_invf[64];
// MMA-ready packed operands (tf32-rounded, tile-permuted)
__device__ float g_xp  [M_TOK * D_];
__device__ float g_attp[M_TOK * QCOLS];
__device__ float g_wqp [D_ * QCOLS];
__device__ float g_wkp [D_ * KVCOLS];
__device__ float g_wvp [D_ * KVCOLS];
__device__ float g_wop [QCOLS * D_];
// flash-ready packed K/V tiles (pre-swizzled smem images, 8192 floats/tile)
__device__ float g_kp  [M_TOK * KVCOLS];
__device__ float g_vp  [M_TOK * KVCOLS];

// ---------------------------------------------------------------------------
// helpers
// ---------------------------------------------------------------------------
__device__ __forceinline__ float to_tf32(float x) {
    uint32_t u;
    asm("cvt.rna.tf32.f32 %0, %1;" : "=r"(u) : "f"(x));
    return __uint_as_float(u);
}
__device__ __forceinline__ uint32_t f2u(float x) { return __float_as_uint(x); }

__device__ __forceinline__ uint32_t smem_u32(const void* p) {
    uint32_t a;
    asm("{ .reg .u64 t; cvta.to.shared.u64 t, %1; cvt.u32.u64 %0, t; }"
        : "=r"(a) : "l"(p));
    return a;
}
__device__ __forceinline__ void cp16(uint32_t dst, const void* src) {
    asm volatile("cp.async.cg.shared.global [%0], [%1], 16;"
                 :: "r"(dst), "l"(src) : "memory");
}
#define CP_COMMIT() asm volatile("cp.async.commit_group;" ::: "memory")
#define CP_WAIT1()  asm volatile("cp.async.wait_group 1;" ::: "memory")
#define CP_WAIT0()  asm volatile("cp.async.wait_group 0;" ::: "memory")

__device__ __forceinline__ void mma_tf32(float4& d,
    uint32_t a0, uint32_t a1, uint32_t a2, uint32_t a3,
    uint32_t b0, uint32_t b1)
{
    asm volatile(
        "mma.sync.aligned.m16n8k8.row.col.f32.tf32.tf32.f32 "
        "{%0,%1,%2,%3}, {%4,%5,%6,%7}, {%8,%9}, {%0,%1,%2,%3};"
        : "+f"(d.x), "+f"(d.y), "+f"(d.z), "+f"(d.w)
        : "r"(a0), "r"(a1), "r"(a2), "r"(a3), "r"(b0), "r"(b1));
}

// ===========================================================================
// pack_all: x activation pack (bny<32) + all 4 weight packs (bny 32..71),
// one launch. Also seeds the RoPE invf table. Same tile layout as R8
// (validated): pos(r,c) = r*16 + 4*((c&3)^(r&3)) + (c>>2).
// ===========================================================================
__global__ void pack_all(
    const float* __restrict__ x,
    const float* __restrict__ wq, const float* __restrict__ wk,
    const float* __restrict__ wv, const float* __restrict__ wo,
    float* __restrict__ xp,
    float* __restrict__ wqp, float* __restrict__ wkp,
    float* __restrict__ wvp, float* __restrict__ wop)
{
    __shared__ __align__(16) float tile[128 * 16];
    const int bk = blockIdx.x, bny = blockIdx.y, tid = threadIdx.x;

    float* dt;
    if (bny < 32) {
        // ---- activation pack: x [4096 x 2048] row-major ----
        if (bk == 0 && bny == 0 && tid < 64)
            g_invf[tid] = (float)(1.0 / pow(1.0e6, (double)tid / 64.0));
        const int bm = bny;
#pragma unroll
        for (int it = 0; it < 2; it++) {
            int idx = tid + (it << 8);
            int r = idx >> 2, aqi = idx & 3;
            float4 v = *(const float4*)(x + (size_t)(bm * 128 + r) * D_
                                          + bk * 16 + (aqi << 2));
            tile[r * 16 + (aqi << 2) + 0] = to_tf32(v.x);
            tile[r * 16 + (aqi << 2) + 1] = to_tf32(v.y);
            tile[r * 16 + (aqi << 2) + 2] = to_tf32(v.z);
            tile[r * 16 + (aqi << 2) + 3] = to_tf32(v.w);
        }
        dt = xp + ((size_t)bm * 128 + bk) * 2048;
    } else {
        // ---- weight pack (transposed): tile row = output col of w ----
        const int bw = bny - 32;
        const float* w; float* dst; int N, bn;
        if (bw < 16)      { w = wq; dst = wqp; N = 2048; bn = bw; }
        else if (bw < 20) { w = wk; dst = wkp; N = 512;  bn = bw - 16; }
        else if (bw < 24) { w = wv; dst = wvp; N = 512;  bn = bw - 20; }
        else              { w = wo; dst = wop; N = 2048; bn = bw - 24; }
#pragma unroll
        for (int it = 0; it < 8; it++) {
            int idx = tid + (it << 8);
            int c = idx >> 7, r = idx & 127;
            tile[r * 16 + c] =
                to_tf32(w[(size_t)(bk * 16 + c) * N + bn * 128 + r]);
        }
        dt = dst + ((size_t)bn * 128 + bk) * 2048;
    }
    __syncthreads();

#pragma unroll
    for (int it = 0; it < 2; it++) {
        int f = tid + (it << 8);
        int r = f >> 2, s = f & 3;
        int x0 = s ^ (r & 3);
        float4 o = make_float4(tile[r * 16 + x0],
                               tile[r * 16 + 4 + x0],
                               tile[r * 16 + 8 + x0],
                               tile[r * 16 + 12 + x0]);
        *(float4*)(dt + (size_t)f * 4) = o;
    }
}

// ===========================================================================
// cp.async TF32 GEMM (unchanged — validated)
// ===========================================================================
__global__ __launch_bounds__(256) void gemm_cp(
    const float* __restrict__ Ap,
    const float* __restrict__ w0, const float* __restrict__ w1,
    const float* __restrict__ w2,
    float* __restrict__ c0p, float* __restrict__ c1p, float* __restrict__ c2p,
    int K, int mode)
{
    __shared__ __align__(16) float sm[3 * 2048 * 2];   // 49152 B
    float* AsF = sm;
    float* BsF = sm + 6144;

    const int tid  = threadIdx.x;
    const int lane = tid & 31;
    const int wid  = tid >> 5;
    const int g    = lane >> 2;
    const int t    = lane & 3;
    const int wrow = wid & 3;
    const int wcol = wid >> 2;
    const int sw4  = t ^ (g & 3);

    const float* Wp; float* C; int Ncols, bn;
    const int bx = blockIdx.x;
    if (mode == 0) {
        if (bx < 16)      { Wp = w0; C = c0p; Ncols = 2048; bn = bx; }
        else if (bx < 20) { Wp = w1; C = c1p; Ncols = 512;  bn = bx - 16; }
        else              { Wp = w2; C = c2p; Ncols = 512;  bn = bx - 20; }
    } else { Wp = w0; C = c0p; Ncols = 2048; bn = bx; }
    const int bm  = blockIdx.y;
    const int nkt = K >> 4;

    const float* Abase = Ap + (size_t)bm * nkt * 2048;
    const float* Bbase = Wp + (size_t)bn * nkt * 2048;
    const uint32_t sA = smem_u32(AsF), sB = smem_u32(BsF);

    float4 c[2][8];
#pragma unroll
    for (int i = 0; i < 2; i++)
#pragma unroll
        for (int j = 0; j < 8; j++) c[i][j] = make_float4(0.f, 0.f, 0.f, 0.f);

#pragma unroll
    for (int s = 0; s < 2; s++) {
        const float* at = Abase + (size_t)s * 2048;
        const float* bt = Bbase + (size_t)s * 2048;
#pragma unroll
        for (int it = 0; it < 2; it++) {
            int f = tid + (it << 8);
            cp16(sA + (uint32_t)(s * 2048 + f * 4) * 4, at + (size_t)f * 4);
            cp16(sB + (uint32_t)(s * 2048 + f * 4) * 4, bt + (size_t)f * 4);
        }
        CP_COMMIT();
    }

    for (int kb = 0; kb < nkt; kb++) {
        CP_WAIT1();
        __syncthreads();

        const int ns = kb + 2;
        if (ns < nkt) {
            const int slot = ns % 3;
            const float* at = Abase + (size_t)ns * 2048;
            const float* bt = Bbase + (size_t)ns * 2048;
#pragma unroll
            for (int it = 0; it < 2; it++) {
                int f = tid + (it << 8);
                cp16(sA + (uint32_t)(slot * 2048 + f * 4) * 4, at + (size_t)f * 4);
                cp16(sB + (uint32_t)(slot * 2048 + f * 4) * 4, bt + (size_t)f * 4);
            }
        }
        CP_COMMIT();

        const float4* As4 = (const float4*)(AsF + (kb % 3) * 2048);
        const float4* Bs4 = (const float4*)(BsF + (kb % 3) * 2048);

        float4 afl[2], afh[2], bf[8];
#pragma unroll
        for (int i = 0; i < 2; i++) {
            int rl = wrow * 32 + i * 16 + g;
            afl[i] = As4[rl * 4 + sw4];
            afh[i] = As4[(rl + 8) * 4 + sw4];
        }
#pragma unroll
        for (int j = 0; j < 8; j++)
            bf[j] = Bs4[(wcol * 64 + j * 8 + g) * 4 + sw4];

#pragma unroll
        for (int i = 0; i < 2; i++) {
            uint32_t a0 = f2u(afl[i].x), a1 = f2u(afh[i].x);
            uint32_t a2 = f2u(afl[i].y), a3 = f2u(afh[i].y);
#pragma unroll
            for (int j = 0; j < 8; j++)
                mma_tf32(c[i][j], a0, a1, a2, a3, f2u(bf[j].x), f2u(bf[j].y));
        }
#pragma unroll
        for (int i = 0; i < 2; i++) {
            uint32_t a0 = f2u(afl[i].z), a1 = f2u(afh[i].z);
            uint32_t a2 = f2u(afl[i].w), a3 = f2u(afh[i].w);
#pragma unroll
            for (int j = 0; j < 8; j++)
                mma_tf32(c[i][j], a0, a1, a2, a3, f2u(bf[j].z), f2u(bf[j].w));
        }
    }
    CP_WAIT0();

    const int row0 = bm * 128, col0 = bn * 128;
#pragma unroll
    for (int i = 0; i < 2; i++) {
        int r = row0 + wrow * 32 + i * 16 + g;
#pragma unroll
        for (int j = 0; j < 8; j++) {
            int cc = col0 + wcol * 64 + j * 8 + 2 * t;
            *(float2*)(C + (size_t)r * Ncols + cc)       = make_float2(c[i][j].x, c[i][j].y);
            *(float2*)(C + (size_t)(r + 8) * Ncols + cc) = make_float2(c[i][j].z, c[i][j].w);
        }
    }
}

// ===========================================================================
// pack_kv — now applies RoPE to K inline (k from the projection is un-roped).
// Same rope formula/order as the validated rope_kernel; V unchanged.
// ===========================================================================
__global__ __launch_bounds__(256) void pack_kv(
    const float* __restrict__ k, const float* __restrict__ v,
    float* __restrict__ kp, float* __restrict__ vp)
{
    __shared__ __align__(16) float stage[16384];
    const int kt  = blockIdx.x;
    const int kvh = blockIdx.y;
    const int b   = blockIdx.z;
    const int tid = threadIdx.x;
    const int s0  = kt * 64;

    const float* Kbase = k + (size_t)b * T_ * KVCOLS + kvh * HD;
    const float* Vbase = v + (size_t)b * T_ * KVCOLS + kvh * HD;

    // K: rope + swizzle. 1024 dim-pairs (s row, d4 in [0,64))
    for (int l = tid; l < 1024; l += 256) {
        int s  = l >> 4;
        int d4 = (l & 15) << 2;
        const float* row = Kbase + (size_t)(s0 + s) * KVCOLS;
        float4 u1 = *(const float4*)(row + d4);
        float4 u2 = *(const float4*)(row + d4 + 64);
        float tp = (float)(s0 + s);
        float o1[4], o2[4];
        float u1a[4] = { u1.x, u1.y, u1.z, u1.w };
        float u2a[4] = { u2.x, u2.y, u2.z, u2.w };
#pragma unroll
        for (int e = 0; e < 4; e++) {
            float sn, cs;
            sincosf(tp * g_invf[d4 + e], &sn, &cs);
            o1[e] = u1a[e] * cs - u2a[e] * sn;
            o2[e] = u2a[e] * cs + u1a[e] * sn;
        }
        int s3 = s & 3;
        int base1 = (d4 >> 4) * 1024 + s * 16 + ((d4 >> 2) & 3);
        int base2 = base1 + 4096;
#pragma unroll
        for (int e = 0; e < 4; e++) {
            stage[base1 + ((e ^ s3) << 2)] = to_tf32(o1[e]);
            stage[base2 + ((e ^ s3) << 2)] = to_tf32(o2[e]);
        }
    }
    // V: plain swizzle (B-layout [dim][token])
    for (int l = tid; l < 2048; l += 256) {
        int s  = l & 63;
        int d4 = (l >> 6) << 2;
        float4 vv = *(const float4*)(Vbase + (size_t)(s0 + s) * KVCOLS + d4);
        int s3 = s & 3;
        int cb = 8192 + (s >> 4) * 2048 + ((s >> 2) & 3);
        stage[cb + (d4 + 0) * 16 + ((s3 ^ 0) << 2)] = to_tf32(vv.x);
        stage[cb + (d4 + 1) * 16 + ((s3 ^ 1) << 2)] = to_tf32(vv.y);
        stage[cb + (d4 + 2) * 16 + ((s3 ^ 2) << 2)] = to_tf32(vv.z);
        stage[cb + (d4 + 3) * 16 + ((s3 ^ 3) << 2)] = to_tf32(vv.w);
    }
    __syncthreads();

    const size_t tbase = (size_t)((b * NKV + kvh) * 32 + kt) * 8192;
    float4* kd = (float4*)(kp + tbase);
    float4* vd = (float4*)(vp + tbase);
    const float4* st4 = (const float4*)stage;
    for (int i = tid; i < 2048; i += 256) kd[i] = st4[i];
    for (int i = tid; i < 2048; i += 256) vd[i] = st4[2048 + i];
}

// ===========================================================================
// TF32 flash attention — BM=64, 128 threads, 2 CTAs/SM (R13-validated core).
// NEW: q-RoPE applied during the Q smem load; epilogue writes g_attp
// directly in packed-tf32 layout (identical values to pack_act(att)).
// smem: Q 8x1028 + K 8x1028 + V 4x2064 = 98816 B.
// ===========================================================================
#define QS_F   (8 * 1028)
#define KS_F   (8 * 1028)
#define VS_F   (4 * 2064)
#define FLASH_SMEM ((QS_F + KS_F + VS_F) * (int)sizeof(float))   // 98816

__global__ __launch_bounds__(128, 2) void flash_tf32(
    const float* __restrict__ Qg, const float* __restrict__ Kp,
    const float* __restrict__ Vp, float* __restrict__ attp)
{
    extern __shared__ float smf[];
    float* Qs = smf;
    float* Ks = Qs + QS_F;
    float* Vs = Ks + KS_F;
    const float4* Qs4 = (const float4*)Qs;
    const float4* Ks4 = (const float4*)Ks;
    const float4* Vs4 = (const float4*)Vs;
    const uint32_t sKs = smem_u32(Ks), sVs = smem_u32(Vs);

    const int tid  = threadIdx.x;
    const int lane = tid & 31;
    const int wid  = tid >> 5;          // 0..3
    const int g    = lane >> 2;
    const int t    = lane & 3;
    const int sw   = t ^ (g & 3);
    const int qb   = (int)gridDim.x - 1 - (int)blockIdx.x;   // heavy first
    const int h    = blockIdx.y;
    const int b    = blockIdx.z;
    const int kvh  = h >> 2;
    const int q0   = qb * 64;
    const int rl   = wid * 16 + g;
    const float scale = 0.08838834764831845f;
    const int s1l  = (lane & 28) | (t >> 1);
    const int s2l  = s1l + 2;
    const bool odd = (t & 1) != 0;

    const float* Qbase = Qg + (size_t)b * T_ * QCOLS + h * HD;
    const float* Ktile = Kp + (size_t)((b * NKV + kvh) * 32) * 8192;
    const float* Vtile = Vp + (size_t)((b * NKV + kvh) * 32) * 8192;

    // ---- prologue: prefetch K[0] then V[0] (separate groups) ----
#pragma unroll
    for (int it = 0; it < 16; it++) {
        int idx = tid + (it << 7);
        int ch = idx >> 8, win = idx & 255;
        cp16(sKs + (uint32_t)(ch * 1028 + win * 4) * 4, Ktile + (size_t)idx * 4);
    }
    CP_COMMIT();
#pragma unroll
    for (int it = 0; it < 16; it++) {
        int idx = tid + (it << 7);
        int ch = idx >> 9, win = idx & 511;
        cp16(sVs + (uint32_t)(ch * 2064 + win * 4) * 4, Vtile + (size_t)idx * 4);
    }
    CP_COMMIT();

    // ---- load Q tile [64 rows][128 dims], applying RoPE inline ----
    for (int l = tid; l < 1024; l += 128) {
        int r  = l >> 4;
        int d4 = (l & 15) << 2;
        const float* row = Qbase + (size_t)(q0 + r) * QCOLS;
        float4 u1 = *(const float4*)(row + d4);
        float4 u2 = *(const float4*)(row + d4 + 64);
        float tp = (float)(q0 + r);
        float o1[4], o2[4];
        float u1a[4] = { u1.x, u1.y, u1.z, u1.w };
        float u2a[4] = { u2.x, u2.y, u2.z, u2.w };
#pragma unroll
        for (int e = 0; e < 4; e++) {
            float sn, cs;
            sincosf(tp * g_invf[d4 + e], &sn, &cs);
            o1[e] = u1a[e] * cs - u2a[e] * sn;
            o2[e] = u2a[e] * cs + u1a[e] * sn;
        }
        int r3 = r & 3;
        int base1 = (d4 >> 4) * 1028 + r * 16 + ((d4 >> 2) & 3);
        int base2 = base1 + 4 * 1028;
#pragma unroll
        for (int e = 0; e < 4; e++) {
            Qs[base1 + ((e ^ r3) << 2)] = to_tf32(o1[e]);
            Qs[base2 + ((e ^ r3) << 2)] = to_tf32(o2[e]);
        }
    }

    CP_WAIT1();            // K[0] landed (V[0] in flight)
    __syncthreads();       // K visible + Q stores done

    float4 o[16];
#pragma unroll
    for (int j = 0; j < 16; j++) o[j] = make_float4(0.f, 0.f, 0.f, 0.f);
    float m0 = -1e30f, m1 = -1e30f, l0 = 0.f, l1 = 0.f;

    for (int kt = 0; kt <= qb; kt++) {
        // ---- S = Q @ K^T ----
        float4 c[8];
#pragma unroll
        for (int j = 0; j < 8; j++) c[j] = make_float4(0.f, 0.f, 0.f, 0.f);

#pragma unroll
        for (int kc = 0; kc < 8; kc++) {
            float4 aL = Qs4[kc * 257 + rl * 4 + sw];
            float4 aH = Qs4[kc * 257 + (rl + 8) * 4 + sw];
            uint32_t x0 = f2u(aL.x), x1 = f2u(aH.x), x2 = f2u(aL.y), x3 = f2u(aH.y);
            uint32_t z0 = f2u(aL.z), z1 = f2u(aH.z), z2 = f2u(aL.w), z3 = f2u(aH.w);
#pragma unroll
            for (int j = 0; j < 8; j++) {
                float4 bv = Ks4[kc * 257 + (8 * j + g) * 4 + sw];
                mma_tf32(c[j], x0, x1, x2, x3, f2u(bv.x), f2u(bv.y));
                mma_tf32(c[j], z0, z1, z2, z3, f2u(bv.z), f2u(bv.w));
            }
        }
        __syncthreads();   // all warps done reading K buffer

        if (kt < qb) {
            const float* src = Ktile + (size_t)(kt + 1) * 8192;
#pragma unroll
            for (int it = 0; it < 16; it++) {
                int idx = tid + (it << 7);
                int ch = idx >> 8, win = idx & 255;
                cp16(sKs + (uint32_t)(ch * 1028 + win * 4) * 4, src + (size_t)idx * 4);
            }
        }
        CP_COMMIT();       // pending: V[kt], K[kt+1]

#pragma unroll
        for (int j = 0; j < 8; j++) {
            c[j].x *= scale; c[j].y *= scale; c[j].z *= scale; c[j].w *= scale;
        }

        const int s0 = kt * 64;
        if (kt == qb) {
            const int row_lo = q0 + rl, row_hi = row_lo + 8;
#pragma unroll
            for (int j = 0; j < 8; j++) {
                int col = s0 + 8 * j + 2 * t;
                if (col     > row_lo) c[j].x = -1e30f;
                if (col + 1 > row_lo) c[j].y = -1e30f;
                if (col     > row_hi) c[j].z = -1e30f;
                if (col + 1 > row_hi) c[j].w = -1e30f;
            }
        }

        // ---- online softmax ----
        float mt0 = -1e30f, mt1 = -1e30f;
#pragma unroll
        for (int j = 0; j < 8; j++) {
            mt0 = fmaxf(mt0, fmaxf(c[j].x, c[j].y));
            mt1 = fmaxf(mt1, fmaxf(c[j].z, c[j].w));
        }
#pragma unroll
        for (int off = 1; off <= 2; off <<= 1) {
            mt0 = fmaxf(mt0, __shfl_xor_sync(0xffffffffu, mt0, off));
            mt1 = fmaxf(mt1, __shfl_xor_sync(0xffffffffu, mt1, off));
        }
        float m0n = fmaxf(m0, mt0), m1n = fmaxf(m1, mt1);
        float corr0 = __expf(m0 - m0n), corr1 = __expf(m1 - m1n);

        float rs0 = 0.f, rs1 = 0.f;
#pragma unroll
        for (int j = 0; j < 8; j++) {
            c[j].x = __expf(c[j].x - m0n);
            c[j].y = __expf(c[j].y - m0n);
            c[j].z = __expf(c[j].z - m1n);
            c[j].w = __expf(c[j].w - m1n);
            rs0 += c[j].x + c[j].y;
            rs1 += c[j].z + c[j].w;
        }
#pragma unroll
        for (int off = 1; off <= 2; off <<= 1) {
            rs0 += __shfl_xor_sync(0xffffffffu, rs0, off);
            rs1 += __shfl_xor_sync(0xffffffffu, rs1, off);
        }
        l0 = l0 * corr0 + rs0;  m0 = m0n;
        l1 = l1 * corr1 + rs1;  m1 = m1n;

#pragma unroll
        for (int j = 0; j < 16; j++) {
            o[j].x *= corr0; o[j].y *= corr0;
            o[j].z *= corr1; o[j].w *= corr1;
        }

        CP_WAIT1();        // V[kt] landed
        __syncthreads();

        // ---- O += P @ V : P fragments via warp shuffles ----
#pragma unroll
        for (int kc = 0; kc < 4; kc++) {
            uint32_t aE[4], aO[4];
#pragma unroll
            for (int half = 0; half < 2; half++) {
                float4 cc = c[2 * kc + half];
                cc.x = to_tf32(cc.x); cc.y = to_tf32(cc.y);
                cc.z = to_tf32(cc.z); cc.w = to_tf32(cc.w);
                float xa = __shfl_sync(0xffffffffu, cc.x, s1l);
                float ya = __shfl_sync(0xffffffffu, cc.y, s1l);
                float za = __shfl_sync(0xffffffffu, cc.z, s1l);
                float wa = __shfl_sync(0xffffffffu, cc.w, s1l);
                float xb = __shfl_sync(0xffffffffu, cc.x, s2l);
                float yb = __shfl_sync(0xffffffffu, cc.y, s2l);
                float zb = __shfl_sync(0xffffffffu, cc.z, s2l);
                float wb = __shfl_sync(0xffffffffu, cc.w, s2l);
                uint32_t* a = half ? aO : aE;
                a[0] = f2u(odd ? ya : xa);
                a[1] = f2u(odd ? wa : za);
                a[2] = f2u(odd ? yb : xb);
                a[3] = f2u(odd ? wb : zb);
            }
#pragma unroll
            for (int j = 0; j < 16; j++) {
                float4 bv = Vs4[kc * 516 + (8 * j + g) * 4 + sw];
                mma_tf32(o[j], aE[0], aE[1], aE[2], aE[3], f2u(bv.x), f2u(bv.y));
                mma_tf32(o[j], aO[0], aO[1], aO[2], aO[3], f2u(bv.z), f2u(bv.w));
            }
        }
        __syncthreads();   // all warps done reading V buffer

        if (kt < qb) {
            const float* src = Vtile + (size_t)(kt + 1) * 8192;
#pragma unroll
            for (int it = 0; it < 16; it++) {
                int idx = tid + (it << 7);
                int ch = idx >> 9, win = idx & 511;
                cp16(sVs + (uint32_t)(ch * 2064 + win * 4) * 4, src + (size_t)idx * 4);
            }
        }
        CP_COMMIT();       // pending: K[kt+1], V[kt+1]

        CP_WAIT1();        // K[kt+1] landed
        __syncthreads();
    }
    CP_WAIT0();

    // ---- epilogue: write packed-tf32 att directly ----
    // att row mg = b*2048 + q0 + rl (+8); packed tile (mg>>7, colg>>4).
    float i0 = 1.0f / l0, i1 = 1.0f / l1;
    const int mgA = b * T_ + q0 + rl;
    const int bm  = mgA >> 7;
    const int rA_ = mgA & 127;
    const int rB_ = rA_ + 8;          // same 128-tile, same (r&3)
    const int r3  = rA_ & 3;
    const int cl_lo = 2 * (t & 1);    // (col&3) for even col
    const int offE = ((cl_lo ^ r3) << 2) + (t >> 1);        // even col, partial
    const int offO = (((cl_lo + 1) ^ r3) << 2) + (t >> 1);  // odd col, partial
    float* db = attp + ((size_t)bm * 128 + h * 8) * 2048;
#pragma unroll
    for (int j = 0; j < 16; j++) {
        float* dt = db + (size_t)(j >> 1) * 2048 + 2 * (j & 1);
        dt[rA_ * 16 + offE] = to_tf32(o[j].x * i0);
        dt[rA_ * 16 + offO] = to_tf32(o[j].y * i0);
        dt[rB_ * 16 + offE] = to_tf32(o[j].z * i1);
        dt[rB_ * 16 + offO] = to_tf32(o[j].w * i1);
    }
}

// ---------------------------------------------------------------------------
// Launch — flash is the 4th launch (profiler capture slot)
// ---------------------------------------------------------------------------
extern "C" void kernel_launch(void* const* d_in, const int* in_sizes, int n_in,
                              void* d_out, int out_size)
{
    const float* x  = (const float*)d_in[0];
    const float* wq = (const float*)d_in[1];
    const float* wk = (const float*)d_in[2];
    const float* wv = (const float*)d_in[3];
    const float* wo = (const float*)d_in[4];
    float* out = (float*)d_out;

    float *q, *k, *v, *xp, *attp, *wqp, *wkp, *wvp, *wop, *kp, *vp;
    cudaGetSymbolAddress((void**)&q,    g_q);
    cudaGetSymbolAddress((void**)&k,    g_k);
    cudaGetSymbolAddress((void**)&v,    g_v);
    cudaGetSymbolAddress((void**)&xp,   g_xp);
    cudaGetSymbolAddress((void**)&attp, g_attp);
    cudaGetSymbolAddress((void**)&wqp,  g_wqp);
    cudaGetSymbolAddress((void**)&wkp,  g_wkp);
    cudaGetSymbolAddress((void**)&wvp,  g_wvp);
    cudaGetSymbolAddress((void**)&wop,  g_wop);
    cudaGetSymbolAddress((void**)&kp,   g_kp);
    cudaGetSymbolAddress((void**)&vp,   g_vp);

    cudaFuncSetAttribute(flash_tf32,
                         cudaFuncAttributeMaxDynamicSharedMemorySize, FLASH_SMEM);

    // [1] pack x + all weights (seeds invf)
    pack_all<<<dim3(128, 72), 256>>>(x, wq, wk, wv, wo,
                                     xp, wqp, wkp, wvp, wop);
    // [2] fused QKV projection (un-roped q,k,v)
    gemm_cp<<<dim3(24, 32), 256>>>(xp, wqp, wkp, wvp, q, k, v, D_, 0);
    // [3] pack K/V into flash-ready tiles (K gets RoPE here)
    pack_kv<<<dim3(32, NKV, B_), 256>>>(k, v, kp, vp);
    // [4] causal GQA flash attention (q-RoPE inline; writes packed attp)
    flash_tf32<<<dim3(T_ / 64, NH, B_), 128, FLASH_SMEM>>>(q, kp, vp, attp);
    // [5] output projection
    gemm_cp<<<dim3(16, 32), 256>>>(attp, wop, nullptr, nullptr,
                                   out, nullptr, nullptr, QCOLS, 1);
}